// round 11
// baseline (speedup 1.0000x reference)
#include <cuda_runtime.h>
#include <cuda_bf16.h>
#include <cuda_fp16.h>
#include <math.h>
#include <stdint.h>

// Problem dims (fixed)
#define BB 2
#define TT 1024
#define RR 2048          // B*T rows
#define EE 256
#define MM 256
#define HH 1024
#define VV 32000
#define WW 8
#define ZK 512           // M+E
#define SK 2048          // W*E

// ================= PTX helpers (arch-agnostic only!) ==========================
__device__ __forceinline__ uint32_t smem_u32(const void* p) {
    uint32_t a;
    asm("{ .reg .u64 t; cvta.to.shared.u64 t, %1; cvt.u32.u64 %0, t; }" : "=r"(a) : "l"(p));
    return a;
}
__device__ __forceinline__ void cp16(uint32_t saddr, const void* g) {
    asm volatile("cp.async.cg.shared.global [%0], [%1], 16;\n" :: "r"(saddr), "l"(g));
}
#define CP_COMMIT() asm volatile("cp.async.commit_group;\n" ::: "memory")
#define CP_WAIT(n)  asm volatile("cp.async.wait_group %0;\n" :: "n"(n) : "memory")

__device__ __forceinline__ void ldmx4(uint32_t* r, uint32_t addr) {
    asm volatile("ldmatrix.sync.aligned.m8n8.x4.shared.b16 {%0,%1,%2,%3}, [%4];"
        : "=r"(r[0]), "=r"(r[1]), "=r"(r[2]), "=r"(r[3]) : "r"(addr));
}
__device__ __forceinline__ void mma_bf16(float* c, const uint32_t* a,
                                         uint32_t b0, uint32_t b1) {
    asm volatile("mma.sync.aligned.m16n8k16.row.col.f32.bf16.bf16.f32 "
        "{%0,%1,%2,%3}, {%4,%5,%6,%7}, {%8,%9}, {%0,%1,%2,%3};"
        : "+f"(c[0]), "+f"(c[1]), "+f"(c[2]), "+f"(c[3])
        : "r"(a[0]), "r"(a[1]), "r"(a[2]), "r"(a[3]), "r"(b0), "r"(b1));
}
__device__ __forceinline__ void mma_f16(float* c, const uint32_t* a,
                                        uint32_t b0, uint32_t b1) {
    asm volatile("mma.sync.aligned.m16n8k16.row.col.f32.f16.f16.f32 "
        "{%0,%1,%2,%3}, {%4,%5,%6,%7}, {%8,%9}, {%0,%1,%2,%3};"
        : "+f"(c[0]), "+f"(c[1]), "+f"(c[2]), "+f"(c[3])
        : "r"(a[0]), "r"(a[1]), "r"(a[2]), "r"(a[3]), "r"(b0), "r"(b1));
}
__device__ __forceinline__ __nv_bfloat162 split_hi2(float x, float y, float& rx, float& ry) {
    __nv_bfloat16 hx = __float2bfloat16(x), hy = __float2bfloat16(y);
    rx = x - __bfloat162float(hx);
    ry = y - __bfloat162float(hy);
    return __nv_bfloat162(hx, hy);
}

// ---------------- scratch (device globals; no allocation allowed) -------------
__device__ float g_x[RR * EE];
__device__ float g_drive[RR * MM];
__device__ float g_loc[(size_t)RR * VV];
__device__ float g_featsA[RR * 3];
__device__ float g_featsB[RR * 3];
// bf16 split activations
__device__ __nv_bfloat16 g_zh[RR * ZK];
__device__ __nv_bfloat16 g_zl[RR * ZK];
__device__ __nv_bfloat16 g_sh[RR * SK];
__device__ __nv_bfloat16 g_sl[RR * SK];
// fp16 hidden outputs + fp16 transposed W2
__device__ __half g_ha16[RR * HH];
__device__ __half g_hb16[RR * HH];
__device__ __half g_w16l[(size_t)VV * HH];
__device__ __half g_w16c[(size_t)VV * HH];
// bf16 split transposed W1
__device__ __nv_bfloat16 g_w1l_h[HH * ZK];
__device__ __nv_bfloat16 g_w1l_l[HH * ZK];
__device__ __nv_bfloat16 g_w1c_h[(size_t)HH * SK];
__device__ __nv_bfloat16 g_w1c_l[(size_t)HH * SK];

// -------- embed: x fp32 + z[:,256:512] split bf16 ----------------------------
__global__ void k_embed(const int* __restrict__ chars, const float* __restrict__ emb) {
    int row = blockIdx.x;
    int c = chars[row];
    const float4* src = (const float4*)(emb + (size_t)c * EE);
    float4* dx = (float4*)(g_x + (size_t)row * EE);
    int i = threadIdx.x;
    float4 v = src[i];
    dx[i] = v;
    float lx, ly, lz, lw;
    __nv_bfloat162 h01 = split_hi2(v.x, v.y, lx, ly);
    __nv_bfloat162 h23 = split_hi2(v.z, v.w, lz, lw);
    size_t o = (size_t)row * ZK + MM + i * 4;
    ((__nv_bfloat162*)(g_zh + o))[0] = h01;
    ((__nv_bfloat162*)(g_zh + o))[1] = h23;
    ((__nv_bfloat162*)(g_zl + o))[0] = __nv_bfloat162(__float2bfloat16(lx), __float2bfloat16(ly));
    ((__nv_bfloat162*)(g_zl + o))[1] = __nv_bfloat162(__float2bfloat16(lz), __float2bfloat16(lw));
}

// -------- decay scan -> z[:,0:256] split bf16 ---------------------------------
__global__ void k_scan(const float* __restrict__ decays) {
    int idx = blockIdx.x * blockDim.x + threadIdx.x;
    if (idx >= BB * MM) return;
    int b = idx >> 8;
    int m = idx & 255;
    float d = decays[m];
    float s = 0.f;
    const float* dr = g_drive + (size_t)b * TT * MM + m;
    __nv_bfloat16* zh = g_zh + (size_t)b * TT * ZK + m;
    __nv_bfloat16* zl = g_zl + (size_t)b * TT * ZK + m;
    for (int t = 0; t < TT; t++) {
        s = fmaf(d, s, dr[(size_t)t * MM]);
        __nv_bfloat16 h = __float2bfloat16(s);
        zh[(size_t)t * ZK] = h;
        zl[(size_t)t * ZK] = __float2bfloat16(s - __bfloat162float(h));
    }
}

// -------- windowed stack -> split bf16 ----------------------------------------
__global__ void k_stack() {
    int row = blockIdx.x;
    int o = blockIdx.y;
    int t = row & (TT - 1);
    size_t dsto = (size_t)row * SK + o * EE + threadIdx.x * 4;
    __nv_bfloat162* dh = (__nv_bfloat162*)(g_sh + dsto);
    __nv_bfloat162* dl = (__nv_bfloat162*)(g_sl + dsto);
    if (t - o >= 0) {
        float4 v = ((const float4*)(g_x + (size_t)(row - o) * EE))[threadIdx.x];
        float lx, ly, lz, lw;
        dh[0] = split_hi2(v.x, v.y, lx, ly);
        dh[1] = split_hi2(v.z, v.w, lz, lw);
        dl[0] = __nv_bfloat162(__float2bfloat16(lx), __float2bfloat16(ly));
        dl[1] = __nv_bfloat162(__float2bfloat16(lz), __float2bfloat16(lw));
    } else {
        __nv_bfloat162 zz(__float2bfloat16(0.f), __float2bfloat16(0.f));
        dh[0] = zz; dh[1] = zz; dl[0] = zz; dl[1] = zz;
    }
}

// ---------------- SIMT fp32 GEMM (drive only) ---------------------------------
#define GBM 128
#define GBN 128
#define GBK 16
__global__ __launch_bounds__(256, 2) void k_gemm(
    const float* __restrict__ A, const float* __restrict__ B,
    float* __restrict__ C, int Ndim, int Kdim)
{
    __shared__ float As[GBK][GBM + 4];
    __shared__ float Bs[GBK][GBN + 4];
    int tid = threadIdx.x;
    int m0 = blockIdx.y * GBM;
    int n0 = blockIdx.x * GBN;
    int ty = tid >> 4, tx = tid & 15;
    float acc[8][8];
#pragma unroll
    for (int i = 0; i < 8; i++)
#pragma unroll
        for (int j = 0; j < 8; j++) acc[i][j] = 0.f;
    for (int k0 = 0; k0 < Kdim; k0 += GBK) {
#pragma unroll
        for (int r = 0; r < 2; r++) {
            int idx = tid + r * 256;
            int ar = idx >> 2, ac4 = idx & 3;
            float4 va = *(const float4*)(A + (size_t)(m0 + ar) * Kdim + k0 + ac4 * 4);
            As[ac4 * 4 + 0][ar] = va.x;
            As[ac4 * 4 + 1][ar] = va.y;
            As[ac4 * 4 + 2][ar] = va.z;
            As[ac4 * 4 + 3][ar] = va.w;
            int br = idx >> 5, bc4 = idx & 31;
            float4 vb = *(const float4*)(B + (size_t)(k0 + br) * Ndim + n0 + bc4 * 4);
            *(float4*)&Bs[br][bc4 * 4] = vb;
        }
        __syncthreads();
#pragma unroll
        for (int kk = 0; kk < GBK; kk++) {
            float a[8], b[8];
            *(float4*)&a[0] = *(const float4*)&As[kk][ty * 8];
            *(float4*)&a[4] = *(const float4*)&As[kk][ty * 8 + 4];
            *(float4*)&b[0] = *(const float4*)&Bs[kk][tx * 8];
            *(float4*)&b[4] = *(const float4*)&Bs[kk][tx * 8 + 4];
#pragma unroll
            for (int i = 0; i < 8; i++)
#pragma unroll
                for (int j = 0; j < 8; j++)
                    acc[i][j] = fmaf(a[i], b[j], acc[i][j]);
        }
        __syncthreads();
    }
#pragma unroll
    for (int i = 0; i < 8; i++) {
        int m = m0 + ty * 8 + i;
#pragma unroll
        for (int j = 0; j < 8; j += 4) {
            int n = n0 + tx * 8 + j;
            float4 v;
            v.x = acc[i][j + 0]; v.y = acc[i][j + 1];
            v.z = acc[i][j + 2]; v.w = acc[i][j + 3];
            *(float4*)(C + (size_t)m * Ndim + n) = v;
        }
    }
}

// ---------- transpose + split W[Krows,Ncols] -> Wt[N,K] bf16 hi/lo ------------
__global__ void k_wsplitT(const float* __restrict__ Wsrc,
                          __nv_bfloat16* __restrict__ Th,
                          __nv_bfloat16* __restrict__ Tl,
                          int Krows, int Ncols) {
    __shared__ float tile[32][33];
    int n0 = blockIdx.x * 32;
    int k0 = blockIdx.y * 32;
    int tx = threadIdx.x, ty = threadIdx.y;
#pragma unroll
    for (int r = 0; r < 32; r += 8)
        tile[ty + r][tx] = Wsrc[(size_t)(k0 + ty + r) * Ncols + n0 + tx];
    __syncthreads();
#pragma unroll
    for (int r = 0; r < 32; r += 8) {
        float v = tile[tx][ty + r];
        __nv_bfloat16 h = __float2bfloat16(v);
        __nv_bfloat16 l = __float2bfloat16(v - __bfloat162float(h));
        size_t o = (size_t)(n0 + ty + r) * Krows + k0 + tx;
        Th[o] = h;
        Tl[o] = l;
    }
}

// ---------- transpose + convert W[Krows,Ncols] -> Wt[N,K] fp16 ----------------
__global__ void k_wconvT(const float* __restrict__ Wsrc,
                         __half* __restrict__ T, int Krows, int Ncols) {
    __shared__ float tile[32][33];
    int n0 = blockIdx.x * 32;
    int k0 = blockIdx.y * 32;
    int tx = threadIdx.x, ty = threadIdx.y;
#pragma unroll
    for (int r = 0; r < 32; r += 8)
        tile[ty + r][tx] = Wsrc[(size_t)(k0 + ty + r) * Ncols + n0 + tx];
    __syncthreads();
#pragma unroll
    for (int r = 0; r < 32; r += 8)
        T[(size_t)(n0 + ty + r) * Krows + k0 + tx] = __float2half_rn(tile[tx][ty + r]);
}

// ===== bf16 3-product hidden GEMM -> fp16 out; CTA tile CTAMx128, BK=32 =======
#define ROWP 80
#define TILB (128 * ROWP)

template<int CTAM, bool RELU>
__global__ __launch_bounds__(256, 2) void k_mma3(
    const __nv_bfloat16* __restrict__ Ah, const __nv_bfloat16* __restrict__ Al,
    const __nv_bfloat16* __restrict__ Bh, const __nv_bfloat16* __restrict__ Bl,
    const float* __restrict__ bias, __half* __restrict__ O,
    int Kdim, int ldO)
{
    constexpr int MROWS = CTAM / 32;
    constexpr int NP = MROWS;
    constexpr int TILA = CTAM * ROWP;
    constexpr int STG = 2 * TILA + 2 * TILB;

    extern __shared__ char smem[];
    uint32_t sb = smem_u32(smem);
    int tid = threadIdx.x;
    int w = tid >> 5, lane = tid & 31;
    int wm = w % MROWS, wn = w / MROWS;
    int m0 = blockIdx.x * CTAM;
    int n0 = blockIdx.y * 128;
    int nit = Kdim / 32;

    float acc[2][2 * NP][4];
#pragma unroll
    for (int a = 0; a < 2; a++)
#pragma unroll
        for (int b = 0; b < 2 * NP; b++)
#pragma unroll
            for (int c = 0; c < 4; c++) acc[a][b][c] = 0.f;

    auto load_stage = [&](int s, int k0) {
        uint32_t base = sb + s * STG;
#pragma unroll
        for (int t = 0; t < CTAM / 64; t++) {
            int idx = tid + t * 256;
            int r = idx >> 2, c = idx & 3;
            uint32_t so = (uint32_t)(r * ROWP + c * 16);
            size_t ga = (size_t)(m0 + r) * Kdim + k0 + c * 8;
            cp16(base + so, Ah + ga);
            cp16(base + TILA + so, Al + ga);
        }
#pragma unroll
        for (int t = 0; t < 2; t++) {
            int idx = tid + t * 256;
            int r = idx >> 2, c = idx & 3;
            uint32_t so = (uint32_t)(r * ROWP + c * 16);
            size_t gb = (size_t)(n0 + r) * Kdim + k0 + c * 8;
            cp16(base + 2 * TILA + so, Bh + gb);
            cp16(base + 2 * TILA + TILB + so, Bl + gb);
        }
        CP_COMMIT();
    };

    load_stage(0, 0);

    int lr = lane & 15, lc = lane >> 4;
#pragma unroll 1
    for (int i = 0; i < nit; i++) {
        int s = i & 1;
        CP_WAIT(0);
        __syncthreads();
        if (i + 1 < nit) load_stage(s ^ 1, (i + 1) * 32);

        uint32_t base = sb + s * STG;
#pragma unroll
        for (int kh = 0; kh < 2; kh++) {
            uint32_t colB = (uint32_t)((kh * 16 + lc * 8) * 2);
            uint32_t ra_h[2][4], ra_l[2][4], rb_h[NP][4], rb_l[NP][4];
#pragma unroll
            for (int mt = 0; mt < 2; mt++)
                ldmx4(ra_h[mt], base + (uint32_t)((wm * 32 + mt * 16 + lr) * ROWP) + colB);
#pragma unroll
            for (int np = 0; np < NP; np++)
                ldmx4(rb_h[np], base + 2 * TILA +
                      (uint32_t)((wn * NP * 16 + np * 16 + lr) * ROWP) + colB);
#pragma unroll
            for (int mt = 0; mt < 2; mt++)
#pragma unroll
                for (int np = 0; np < NP; np++) {
                    mma_bf16(acc[mt][2 * np],     ra_h[mt], rb_h[np][0], rb_h[np][2]);
                    mma_bf16(acc[mt][2 * np + 1], ra_h[mt], rb_h[np][1], rb_h[np][3]);
                }
#pragma unroll
            for (int mt = 0; mt < 2; mt++)
                ldmx4(ra_l[mt], base + TILA +
                      (uint32_t)((wm * 32 + mt * 16 + lr) * ROWP) + colB);
#pragma unroll
            for (int mt = 0; mt < 2; mt++)
#pragma unroll
                for (int np = 0; np < NP; np++) {
                    mma_bf16(acc[mt][2 * np],     ra_l[mt], rb_h[np][0], rb_h[np][2]);
                    mma_bf16(acc[mt][2 * np + 1], ra_l[mt], rb_h[np][1], rb_h[np][3]);
                }
#pragma unroll
            for (int np = 0; np < NP; np++)
                ldmx4(rb_l[np], base + 2 * TILA + TILB +
                      (uint32_t)((wn * NP * 16 + np * 16 + lr) * ROWP) + colB);
#pragma unroll
            for (int mt = 0; mt < 2; mt++)
#pragma unroll
                for (int np = 0; np < NP; np++) {
                    mma_bf16(acc[mt][2 * np],     ra_h[mt], rb_l[np][0], rb_l[np][2]);
                    mma_bf16(acc[mt][2 * np + 1], ra_h[mt], rb_l[np][1], rb_l[np][3]);
                }
        }
        __syncthreads();
    }

    int qr = lane >> 2, qc = lane & 3;
#pragma unroll
    for (int mt = 0; mt < 2; mt++) {
        int r0 = m0 + wm * 32 + mt * 16 + qr;
#pragma unroll
        for (int nt = 0; nt < 2 * NP; nt++) {
            int cidx = n0 + wn * NP * 16 + nt * 8 + qc * 2;
            float b0 = __ldg(bias + cidx), b1 = __ldg(bias + cidx + 1);
            float v00 = acc[mt][nt][0] + b0, v01 = acc[mt][nt][1] + b1;
            float v10 = acc[mt][nt][2] + b0, v11 = acc[mt][nt][3] + b1;
            if (RELU) {
                v00 = fmaxf(v00, 0.f); v01 = fmaxf(v01, 0.f);
                v10 = fmaxf(v10, 0.f); v11 = fmaxf(v11, 0.f);
            }
            *(__half2*)(O + (size_t)r0 * ldO + cidx) = __floats2half2_rn(v00, v01);
            *(__half2*)(O + (size_t)(r0 + 8) * ldO + cidx) = __floats2half2_rn(v10, v11);
        }
    }
}

// ===== fp16 logit GEMM v2: CTA 128x256, 256 thr, warp tile 64x64, 4-stage =====
// Arithmetic intensity doubled vs 32x64 tiles: 8 LDSM.x4 per 64 HMMA per warp-kh.
#define F3TILA (128 * ROWP)              // 10240
#define F3TILB (256 * ROWP)              // 20480
#define F3STG (F3TILA + F3TILB)          // 30720
#define F3SMEM (4 * F3STG)               // 122880

__global__ __launch_bounds__(256, 1) void k_mmaf16(
    const __half* __restrict__ A, const __half* __restrict__ B,
    const float* __restrict__ bias, float* __restrict__ C, int Kdim, int ldC)
{
    extern __shared__ char smem[];
    uint32_t sb = smem_u32(smem);
    int tid = threadIdx.x;
    int w = tid >> 5, lane = tid & 31;
    int wm = w & 1, wn = w >> 1;            // warp tile 64x64; 2x4 warps
    int m0 = blockIdx.x * 128;
    int n0 = blockIdx.y * 256;
    int nit = Kdim / 32;

    float acc[4][8][4];                     // 128 regs
#pragma unroll
    for (int a = 0; a < 4; a++)
#pragma unroll
        for (int b = 0; b < 8; b++)
#pragma unroll
            for (int c = 0; c < 4; c++) acc[a][b][c] = 0.f;

    auto load_stage = [&](int s, int k0) {
        uint32_t base = sb + s * F3STG;
#pragma unroll
        for (int t = 0; t < 2; t++) {
            int idx = tid + t * 256;                       // 128 rows x 4 chunks
            int r = idx >> 2, c = idx & 3;
            cp16(base + (uint32_t)(r * ROWP + c * 16),
                 A + (size_t)(m0 + r) * Kdim + k0 + c * 8);
        }
#pragma unroll
        for (int t = 0; t < 4; t++) {
            int idx = tid + t * 256;                       // 256 rows x 4 chunks
            int r = idx >> 2, c = idx & 3;
            cp16(base + F3TILA + (uint32_t)(r * ROWP + c * 16),
                 B + (size_t)(n0 + r) * Kdim + k0 + c * 8);
        }
        CP_COMMIT();
    };

    load_stage(0, 0);
    if (nit > 1) load_stage(1, 32);
    if (nit > 2) load_stage(2, 64);

    int lr = lane & 15, lc = lane >> 4;
#pragma unroll 1
    for (int i = 0; i < nit; i++) {
        // exact tail waits: pending groups = min(3, nit - i)
        if (i + 3 <= nit) { CP_WAIT(2); }
        else if (i + 2 == nit) { CP_WAIT(1); }
        else { CP_WAIT(0); }
        __syncthreads();
        if (i + 3 < nit) load_stage((i + 3) & 3, (i + 3) * 32);

        uint32_t base = sb + (i & 3) * F3STG;
#pragma unroll
        for (int kh = 0; kh < 2; kh++) {
            uint32_t colB = (uint32_t)((kh * 16 + lc * 8) * 2);
            uint32_t ra[4][4], rb[4][4];
#pragma unroll
            for (int mt = 0; mt < 4; mt++)
                ldmx4(ra[mt], base + (uint32_t)((wm * 64 + mt * 16 + lr) * ROWP) + colB);
#pragma unroll
            for (int np = 0; np < 4; np++)
                ldmx4(rb[np], base + F3TILA +
                      (uint32_t)((wn * 64 + np * 16 + lr) * ROWP) + colB);
#pragma unroll
            for (int mt = 0; mt < 4; mt++)
#pragma unroll
                for (int np = 0; np < 4; np++) {
                    mma_f16(acc[mt][2 * np],     ra[mt], rb[np][0], rb[np][2]);
                    mma_f16(acc[mt][2 * np + 1], ra[mt], rb[np][1], rb[np][3]);
                }
        }
        // no bottom barrier: next iter's top barrier orders laggards vs the
        // stage overwritten then (4-deep ring)
    }

    int qr = lane >> 2, qc = lane & 3;
#pragma unroll
    for (int mt = 0; mt < 4; mt++) {
        int r0 = m0 + wm * 64 + mt * 16 + qr;
#pragma unroll
        for (int nt = 0; nt < 8; nt++) {
            int cidx = n0 + wn * 64 + nt * 8 + qc * 2;
            float b0 = __ldg(bias + cidx), b1 = __ldg(bias + cidx + 1);
            *(float2*)(C + (size_t)r0 * ldC + cidx) =
                make_float2(acc[mt][nt][0] + b0, acc[mt][nt][1] + b1);
            *(float2*)(C + (size_t)(r0 + 8) * ldC + cidx) =
                make_float2(acc[mt][nt][2] + b0, acc[mt][nt][3] + b1);
        }
    }
}

// ---------------- block reduce ------------------------------------------------
__device__ __forceinline__ float blockReduce(float v, bool domax) {
    __shared__ float sh[8];
    int lane = threadIdx.x & 31;
    int wp = threadIdx.x >> 5;
#pragma unroll
    for (int o = 16; o; o >>= 1) {
        float t = __shfl_xor_sync(0xffffffffu, v, o);
        v = domax ? fmaxf(v, t) : (v + t);
    }
    if (lane == 0) sh[wp] = v;
    __syncthreads();
    float r = sh[lane & 7];
#pragma unroll
    for (int o = 4; o; o >>= 1) {
        float t = __shfl_xor_sync(0xffffffffu, r, o);
        r = domax ? fmaxf(r, t) : (r + t);
    }
    __syncthreads();
    return r;
}

// ------------- per-matrix logit stats: ent, max, var -> feats[row*3] ----------
__global__ void k_stats(const float* __restrict__ src, float* __restrict__ feats) {
    int row = blockIdx.x;
    const float4* p = (const float4*)(src + (size_t)row * VV);
    float mx = -INFINITY, sum = 0.f, sq = 0.f;
    for (int i = threadIdx.x; i < VV / 4; i += 256) {
        float4 v = p[i];
        mx = fmaxf(mx, fmaxf(fmaxf(v.x, v.y), fmaxf(v.z, v.w)));
        sum += (v.x + v.y) + (v.z + v.w);
        sq += v.x * v.x + v.y * v.y + v.z * v.z + v.w * v.w;
    }
    mx  = blockReduce(mx, true);
    sum = blockReduce(sum, false);
    sq  = blockReduce(sq, false);
    float se = 0.f, sl = 0.f;
    for (int i = threadIdx.x; i < VV / 4; i += 256) {
        float4 v = p[i];
        float e;
        e = __expf(v.x - mx); se += e; sl += e * v.x;
        e = __expf(v.y - mx); se += e; sl += e * v.y;
        e = __expf(v.z - mx); se += e; sl += e * v.z;
        e = __expf(v.w - mx); se += e; sl += e * v.w;
    }
    se = blockReduce(se, false);
    sl = blockReduce(sl, false);
    if (threadIdx.x == 0) {
        float lse = mx + logf(se);
        float mean = sum * (1.f / VV);
        feats[row * 3 + 0] = lse - sl / se;
        feats[row * 3 + 1] = mx;
        feats[row * 3 + 2] = sq * (1.f / VV) - mean * mean;
    }
}

// ------------- gate from feats + single-pass mix (in place on out) ------------
__global__ void k_mix(float* __restrict__ out,
                      const float* __restrict__ gw, const float* __restrict__ gb,
                      const float* __restrict__ fA, const float* __restrict__ fB)
{
    int row = blockIdx.x;
    float z = __ldg(gb);
#pragma unroll
    for (int i = 0; i < 3; i++) z = fmaf(__ldg(fA + row * 3 + i), __ldg(gw + i), z);
#pragma unroll
    for (int i = 0; i < 3; i++) z = fmaf(__ldg(fB + row * 3 + i), __ldg(gw + 3 + i), z);
    float g = 1.f / (1.f + expf(-z));

    float4* po = (float4*)(out + (size_t)row * VV);
    const float4* pc = (const float4*)(g_loc + (size_t)row * VV);
    for (int i = threadIdx.x; i < VV / 4; i += 256) {
        float4 a = po[i];
        float4 c = pc[i];
        float4 r;
        r.x = fmaf(g, a.x - c.x, c.x);
        r.y = fmaf(g, a.y - c.y, c.y);
        r.z = fmaf(g, a.z - c.z, c.z);
        r.w = fmaf(g, a.w - c.w, c.w);
        po[i] = r;
    }
}

// ---------------- launcher (two-stream overlapped graph) ----------------------
extern "C" void kernel_launch(void* const* d_in, const int* in_sizes, int n_in,
                              void* d_out, int out_size)
{
    const int*   chars   = (const int*)  d_in[0];
    const float* emb     = (const float*)d_in[1];
    const float* in_proj = (const float*)d_in[2];
    const float* decays  = (const float*)d_in[3];
    const float* lin_W1  = (const float*)d_in[4];
    const float* lin_b1  = (const float*)d_in[5];
    const float* lin_W2  = (const float*)d_in[6];
    const float* lin_b2  = (const float*)d_in[7];
    const float* loc_W1  = (const float*)d_in[8];
    const float* loc_b1  = (const float*)d_in[9];
    const float* loc_W2  = (const float*)d_in[10];
    const float* loc_b2  = (const float*)d_in[11];
    const float* gate_W  = (const float*)d_in[12];
    const float* gate_b  = (const float*)d_in[13];
    float* out = (float*)d_out;

    float *px, *pdrive, *ploc, *pfA, *pfB;
    __nv_bfloat16 *pzh, *pzl, *psh, *psl;
    __nv_bfloat16 *pw1lh, *pw1ll, *pw1ch, *pw1cl;
    __half *pha, *phb, *pwl, *pwc;
    cudaGetSymbolAddress((void**)&px,     g_x);
    cudaGetSymbolAddress((void**)&pdrive, g_drive);
    cudaGetSymbolAddress((void**)&ploc,   g_loc);
    cudaGetSymbolAddress((void**)&pfA,    g_featsA);
    cudaGetSymbolAddress((void**)&pfB,    g_featsB);
    cudaGetSymbolAddress((void**)&pzh,    g_zh);
    cudaGetSymbolAddress((void**)&pzl,    g_zl);
    cudaGetSymbolAddress((void**)&psh,    g_sh);
    cudaGetSymbolAddress((void**)&psl,    g_sl);
    cudaGetSymbolAddress((void**)&pha,    g_ha16);
    cudaGetSymbolAddress((void**)&phb,    g_hb16);
    cudaGetSymbolAddress((void**)&pwl,    g_w16l);
    cudaGetSymbolAddress((void**)&pwc,    g_w16c);
    cudaGetSymbolAddress((void**)&pw1lh,  g_w1l_h);
    cudaGetSymbolAddress((void**)&pw1ll,  g_w1l_l);
    cudaGetSymbolAddress((void**)&pw1ch,  g_w1c_h);
    cudaGetSymbolAddress((void**)&pw1cl,  g_w1c_l);

    constexpr int SM64 = 2 * (2 * 64 * ROWP + 2 * TILB);   // 61440
    static cudaStream_t s1 = nullptr;
    static cudaEvent_t e0 = nullptr, e1 = nullptr;
    static bool init_done = false;
    if (!init_done) {
        cudaFuncSetAttribute(k_mma3<64, true>, cudaFuncAttributeMaxDynamicSharedMemorySize, SM64);
        cudaFuncSetAttribute(k_mmaf16, cudaFuncAttributeMaxDynamicSharedMemorySize, F3SMEM);
        cudaStreamCreateWithFlags(&s1, cudaStreamNonBlocking);
        cudaEventCreateWithFlags(&e0, cudaEventDisableTiming);
        cudaEventCreateWithFlags(&e1, cudaEventDisableTiming);
        init_done = true;
    }

    // head (s0): embed fills x + z-embedding half
    k_embed<<<RR, 64>>>(chars, emb);
    cudaEventRecord(e0, 0);
    cudaStreamWaitEvent(s1, e0, 0);

    // ---- s1: loc path ----
    k_stack<<<dim3(RR, WW), 64, 0, s1>>>();
    k_wsplitT<<<dim3(HH / 32, SK / 32), dim3(32, 8), 0, s1>>>(loc_W1, pw1ch, pw1cl, SK, HH);
    k_mma3<64, true><<<dim3(RR / 64, HH / 128), 256, SM64, s1>>>(
        psh, psl, pw1ch, pw1cl, loc_b1, phb, SK, HH);
    k_wconvT<<<dim3(VV / 32, HH / 32), dim3(32, 8), 0, s1>>>(loc_W2, pwc, HH, VV);
    k_mmaf16<<<dim3(RR / 128, VV / 256), 256, F3SMEM, s1>>>(phb, pwc, loc_b2, ploc, HH, VV);
    k_stats<<<RR, 256, 0, s1>>>(ploc, pfB);
    cudaEventRecord(e1, s1);

    // ---- s0: lin path ----
    k_gemm<<<dim3(MM / GBN, RR / GBM), 256>>>(px, in_proj, pdrive, MM, EE);
    k_scan<<<2, 256>>>(decays);
    k_wsplitT<<<dim3(HH / 32, ZK / 32), dim3(32, 8)>>>(lin_W1, pw1lh, pw1ll, ZK, HH);
    k_mma3<64, true><<<dim3(RR / 64, HH / 128), 256, SM64>>>(
        pzh, pzl, pw1lh, pw1ll, lin_b1, pha, ZK, HH);
    k_wconvT<<<dim3(VV / 32, HH / 32), dim3(32, 8)>>>(lin_W2, pwl, HH, VV);
    k_mmaf16<<<dim3(RR / 128, VV / 256), 256, F3SMEM>>>(pha, pwl, lin_b2, out, HH, VV);
    k_stats<<<RR, 256>>>(out, pfA);

    // ---- join + mix (s0) ----
    cudaStreamWaitEvent(0, e1, 0);
    k_mix<<<RR, 256>>>(out, gate_W, gate_b, pfA, pfB);
}

// round 12
// speedup vs baseline: 1.1733x; 1.1733x over previous
#include <cuda_runtime.h>
#include <cuda_bf16.h>
#include <cuda_fp16.h>
#include <math.h>
#include <stdint.h>

// Problem dims (fixed)
#define BB 2
#define TT 1024
#define RR 2048          // B*T rows
#define EE 256
#define MM 256
#define HH 1024
#define VV 32000
#define WW 8
#define ZK 512           // M+E
#define SK 2048          // W*E

// ================= PTX helpers (arch-agnostic only!) ==========================
__device__ __forceinline__ uint32_t smem_u32(const void* p) {
    uint32_t a;
    asm("{ .reg .u64 t; cvta.to.shared.u64 t, %1; cvt.u32.u64 %0, t; }" : "=r"(a) : "l"(p));
    return a;
}
__device__ __forceinline__ void cp16(uint32_t saddr, const void* g) {
    asm volatile("cp.async.cg.shared.global [%0], [%1], 16;\n" :: "r"(saddr), "l"(g));
}
#define CP_COMMIT() asm volatile("cp.async.commit_group;\n" ::: "memory")
#define CP_WAIT(n)  asm volatile("cp.async.wait_group %0;\n" :: "n"(n) : "memory")

__device__ __forceinline__ void ldmx4(uint32_t* r, uint32_t addr) {
    asm volatile("ldmatrix.sync.aligned.m8n8.x4.shared.b16 {%0,%1,%2,%3}, [%4];"
        : "=r"(r[0]), "=r"(r[1]), "=r"(r[2]), "=r"(r[3]) : "r"(addr));
}
__device__ __forceinline__ void mma_bf16(float* c, const uint32_t* a,
                                         uint32_t b0, uint32_t b1) {
    asm volatile("mma.sync.aligned.m16n8k16.row.col.f32.bf16.bf16.f32 "
        "{%0,%1,%2,%3}, {%4,%5,%6,%7}, {%8,%9}, {%0,%1,%2,%3};"
        : "+f"(c[0]), "+f"(c[1]), "+f"(c[2]), "+f"(c[3])
        : "r"(a[0]), "r"(a[1]), "r"(a[2]), "r"(a[3]), "r"(b0), "r"(b1));
}
__device__ __forceinline__ void mma_f16(float* c, const uint32_t* a,
                                        uint32_t b0, uint32_t b1) {
    asm volatile("mma.sync.aligned.m16n8k16.row.col.f32.f16.f16.f32 "
        "{%0,%1,%2,%3}, {%4,%5,%6,%7}, {%8,%9}, {%0,%1,%2,%3};"
        : "+f"(c[0]), "+f"(c[1]), "+f"(c[2]), "+f"(c[3])
        : "r"(a[0]), "r"(a[1]), "r"(a[2]), "r"(a[3]), "r"(b0), "r"(b1));
}
__device__ __forceinline__ __nv_bfloat162 split_hi2(float x, float y, float& rx, float& ry) {
    __nv_bfloat16 hx = __float2bfloat16(x), hy = __float2bfloat16(y);
    rx = x - __bfloat162float(hx);
    ry = y - __bfloat162float(hy);
    return __nv_bfloat162(hx, hy);
}
// ordered-uint encoding for float atomicMax
__device__ __forceinline__ unsigned enc_max(float x) {
    unsigned b = __float_as_uint(x);
    return (b >> 31) ? ~b : (b | 0x80000000u);
}
__device__ __forceinline__ float dec_max(unsigned e) {
    return (e & 0x80000000u) ? __uint_as_float(e & 0x7fffffffu) : __uint_as_float(~e);
}

// ---------------- scratch (device globals; no allocation allowed) -------------
__device__ float g_x[RR * EE];
__device__ float g_drive[RR * MM];
__device__ float g_loc[(size_t)RR * VV];
// fused logit-stat accumulators: per row {se, sl, sum, sq} + encoded max
__device__ unsigned g_mxA[RR];
__device__ unsigned g_mxB[RR];
__device__ float g_smA[RR * 4];
__device__ float g_smB[RR * 4];
// bf16 split activations
__device__ __nv_bfloat16 g_zh[RR * ZK];
__device__ __nv_bfloat16 g_zl[RR * ZK];
__device__ __nv_bfloat16 g_sh[RR * SK];
__device__ __nv_bfloat16 g_sl[RR * SK];
// fp16 hidden outputs + fp16 transposed W2
__device__ __half g_ha16[RR * HH];
__device__ __half g_hb16[RR * HH];
__device__ __half g_w16l[(size_t)VV * HH];
__device__ __half g_w16c[(size_t)VV * HH];
// bf16 split transposed W1
__device__ __nv_bfloat16 g_w1l_h[HH * ZK];
__device__ __nv_bfloat16 g_w1l_l[HH * ZK];
__device__ __nv_bfloat16 g_w1c_h[(size_t)HH * SK];
__device__ __nv_bfloat16 g_w1c_l[(size_t)HH * SK];

// -------- zero the stat accumulators (graph-replay safe) ----------------------
__global__ void k_zero() {
    int i = blockIdx.x * 256 + threadIdx.x;
    if (i < RR) { g_mxA[i] = 0x007fffffu; g_mxB[i] = 0x007fffffu; }  // enc(-inf)
    if (i < RR * 4) { g_smA[i] = 0.f; g_smB[i] = 0.f; }
}

// -------- embed: x fp32 + z[:,256:512] split bf16 ----------------------------
__global__ void k_embed(const int* __restrict__ chars, const float* __restrict__ emb) {
    int row = blockIdx.x;
    int c = chars[row];
    const float4* src = (const float4*)(emb + (size_t)c * EE);
    float4* dx = (float4*)(g_x + (size_t)row * EE);
    int i = threadIdx.x;
    float4 v = src[i];
    dx[i] = v;
    float lx, ly, lz, lw;
    __nv_bfloat162 h01 = split_hi2(v.x, v.y, lx, ly);
    __nv_bfloat162 h23 = split_hi2(v.z, v.w, lz, lw);
    size_t o = (size_t)row * ZK + MM + i * 4;
    ((__nv_bfloat162*)(g_zh + o))[0] = h01;
    ((__nv_bfloat162*)(g_zh + o))[1] = h23;
    ((__nv_bfloat162*)(g_zl + o))[0] = __nv_bfloat162(__float2bfloat16(lx), __float2bfloat16(ly));
    ((__nv_bfloat162*)(g_zl + o))[1] = __nv_bfloat162(__float2bfloat16(lz), __float2bfloat16(lw));
}

// -------- decay scan -> z[:,0:256] split bf16 ---------------------------------
__global__ void k_scan(const float* __restrict__ decays) {
    int idx = blockIdx.x * blockDim.x + threadIdx.x;
    if (idx >= BB * MM) return;
    int b = idx >> 8;
    int m = idx & 255;
    float d = decays[m];
    float s = 0.f;
    const float* dr = g_drive + (size_t)b * TT * MM + m;
    __nv_bfloat16* zh = g_zh + (size_t)b * TT * ZK + m;
    __nv_bfloat16* zl = g_zl + (size_t)b * TT * ZK + m;
    for (int t = 0; t < TT; t++) {
        s = fmaf(d, s, dr[(size_t)t * MM]);
        __nv_bfloat16 h = __float2bfloat16(s);
        zh[(size_t)t * ZK] = h;
        zl[(size_t)t * ZK] = __float2bfloat16(s - __bfloat162float(h));
    }
}

// -------- windowed stack -> split bf16 ----------------------------------------
__global__ void k_stack() {
    int row = blockIdx.x;
    int o = blockIdx.y;
    int t = row & (TT - 1);
    size_t dsto = (size_t)row * SK + o * EE + threadIdx.x * 4;
    __nv_bfloat162* dh = (__nv_bfloat162*)(g_sh + dsto);
    __nv_bfloat162* dl = (__nv_bfloat162*)(g_sl + dsto);
    if (t - o >= 0) {
        float4 v = ((const float4*)(g_x + (size_t)(row - o) * EE))[threadIdx.x];
        float lx, ly, lz, lw;
        dh[0] = split_hi2(v.x, v.y, lx, ly);
        dh[1] = split_hi2(v.z, v.w, lz, lw);
        dl[0] = __nv_bfloat162(__float2bfloat16(lx), __float2bfloat16(ly));
        dl[1] = __nv_bfloat162(__float2bfloat16(lz), __float2bfloat16(lw));
    } else {
        __nv_bfloat162 zz(__float2bfloat16(0.f), __float2bfloat16(0.f));
        dh[0] = zz; dh[1] = zz; dl[0] = zz; dl[1] = zz;
    }
}

// ---------------- SIMT fp32 GEMM (drive only) ---------------------------------
#define GBM 128
#define GBN 128
#define GBK 16
__global__ __launch_bounds__(256, 2) void k_gemm(
    const float* __restrict__ A, const float* __restrict__ B,
    float* __restrict__ C, int Ndim, int Kdim)
{
    __shared__ float As[GBK][GBM + 4];
    __shared__ float Bs[GBK][GBN + 4];
    int tid = threadIdx.x;
    int m0 = blockIdx.y * GBM;
    int n0 = blockIdx.x * GBN;
    int ty = tid >> 4, tx = tid & 15;
    float acc[8][8];
#pragma unroll
    for (int i = 0; i < 8; i++)
#pragma unroll
        for (int j = 0; j < 8; j++) acc[i][j] = 0.f;
    for (int k0 = 0; k0 < Kdim; k0 += GBK) {
#pragma unroll
        for (int r = 0; r < 2; r++) {
            int idx = tid + r * 256;
            int ar = idx >> 2, ac4 = idx & 3;
            float4 va = *(const float4*)(A + (size_t)(m0 + ar) * Kdim + k0 + ac4 * 4);
            As[ac4 * 4 + 0][ar] = va.x;
            As[ac4 * 4 + 1][ar] = va.y;
            As[ac4 * 4 + 2][ar] = va.z;
            As[ac4 * 4 + 3][ar] = va.w;
            int br = idx >> 5, bc4 = idx & 31;
            float4 vb = *(const float4*)(B + (size_t)(k0 + br) * Ndim + n0 + bc4 * 4);
            *(float4*)&Bs[br][bc4 * 4] = vb;
        }
        __syncthreads();
#pragma unroll
        for (int kk = 0; kk < GBK; kk++) {
            float a[8], b[8];
            *(float4*)&a[0] = *(const float4*)&As[kk][ty * 8];
            *(float4*)&a[4] = *(const float4*)&As[kk][ty * 8 + 4];
            *(float4*)&b[0] = *(const float4*)&Bs[kk][tx * 8];
            *(float4*)&b[4] = *(const float4*)&Bs[kk][tx * 8 + 4];
#pragma unroll
            for (int i = 0; i < 8; i++)
#pragma unroll
                for (int j = 0; j < 8; j++)
                    acc[i][j] = fmaf(a[i], b[j], acc[i][j]);
        }
        __syncthreads();
    }
#pragma unroll
    for (int i = 0; i < 8; i++) {
        int m = m0 + ty * 8 + i;
#pragma unroll
        for (int j = 0; j < 8; j += 4) {
            int n = n0 + tx * 8 + j;
            float4 v;
            v.x = acc[i][j + 0]; v.y = acc[i][j + 1];
            v.z = acc[i][j + 2]; v.w = acc[i][j + 3];
            *(float4*)(C + (size_t)m * Ndim + n) = v;
        }
    }
}

// ---------- transpose + split W[Krows,Ncols] -> Wt[N,K] bf16 hi/lo ------------
__global__ void k_wsplitT(const float* __restrict__ Wsrc,
                          __nv_bfloat16* __restrict__ Th,
                          __nv_bfloat16* __restrict__ Tl,
                          int Krows, int Ncols) {
    __shared__ float tile[32][33];
    int n0 = blockIdx.x * 32;
    int k0 = blockIdx.y * 32;
    int tx = threadIdx.x, ty = threadIdx.y;
#pragma unroll
    for (int r = 0; r < 32; r += 8)
        tile[ty + r][tx] = Wsrc[(size_t)(k0 + ty + r) * Ncols + n0 + tx];
    __syncthreads();
#pragma unroll
    for (int r = 0; r < 32; r += 8) {
        float v = tile[tx][ty + r];
        __nv_bfloat16 h = __float2bfloat16(v);
        __nv_bfloat16 l = __float2bfloat16(v - __bfloat162float(h));
        size_t o = (size_t)(n0 + ty + r) * Krows + k0 + tx;
        Th[o] = h;
        Tl[o] = l;
    }
}

// ---------- transpose + convert W[Krows,Ncols] -> Wt[N,K] fp16 ----------------
__global__ void k_wconvT(const float* __restrict__ Wsrc,
                         __half* __restrict__ T, int Krows, int Ncols) {
    __shared__ float tile[32][33];
    int n0 = blockIdx.x * 32;
    int k0 = blockIdx.y * 32;
    int tx = threadIdx.x, ty = threadIdx.y;
#pragma unroll
    for (int r = 0; r < 32; r += 8)
        tile[ty + r][tx] = Wsrc[(size_t)(k0 + ty + r) * Ncols + n0 + tx];
    __syncthreads();
#pragma unroll
    for (int r = 0; r < 32; r += 8)
        T[(size_t)(n0 + ty + r) * Krows + k0 + tx] = __float2half_rn(tile[tx][ty + r]);
}

// ===== bf16 3-product hidden GEMM -> fp16 out; CTA tile CTAMx128, BK=32 =======
#define ROWP 80
#define TILB (128 * ROWP)

template<int CTAM, bool RELU>
__global__ __launch_bounds__(256, 2) void k_mma3(
    const __nv_bfloat16* __restrict__ Ah, const __nv_bfloat16* __restrict__ Al,
    const __nv_bfloat16* __restrict__ Bh, const __nv_bfloat16* __restrict__ Bl,
    const float* __restrict__ bias, __half* __restrict__ O,
    int Kdim, int ldO)
{
    constexpr int MROWS = CTAM / 32;
    constexpr int NP = MROWS;
    constexpr int TILA = CTAM * ROWP;
    constexpr int STG = 2 * TILA + 2 * TILB;

    extern __shared__ char smem[];
    uint32_t sb = smem_u32(smem);
    int tid = threadIdx.x;
    int w = tid >> 5, lane = tid & 31;
    int wm = w % MROWS, wn = w / MROWS;
    int m0 = blockIdx.x * CTAM;
    int n0 = blockIdx.y * 128;
    int nit = Kdim / 32;

    float acc[2][2 * NP][4];
#pragma unroll
    for (int a = 0; a < 2; a++)
#pragma unroll
        for (int b = 0; b < 2 * NP; b++)
#pragma unroll
            for (int c = 0; c < 4; c++) acc[a][b][c] = 0.f;

    auto load_stage = [&](int s, int k0) {
        uint32_t base = sb + s * STG;
#pragma unroll
        for (int t = 0; t < CTAM / 64; t++) {
            int idx = tid + t * 256;
            int r = idx >> 2, c = idx & 3;
            uint32_t so = (uint32_t)(r * ROWP + c * 16);
            size_t ga = (size_t)(m0 + r) * Kdim + k0 + c * 8;
            cp16(base + so, Ah + ga);
            cp16(base + TILA + so, Al + ga);
        }
#pragma unroll
        for (int t = 0; t < 2; t++) {
            int idx = tid + t * 256;
            int r = idx >> 2, c = idx & 3;
            uint32_t so = (uint32_t)(r * ROWP + c * 16);
            size_t gb = (size_t)(n0 + r) * Kdim + k0 + c * 8;
            cp16(base + 2 * TILA + so, Bh + gb);
            cp16(base + 2 * TILA + TILB + so, Bl + gb);
        }
        CP_COMMIT();
    };

    load_stage(0, 0);

    int lr = lane & 15, lc = lane >> 4;
#pragma unroll 1
    for (int i = 0; i < nit; i++) {
        int s = i & 1;
        CP_WAIT(0);
        __syncthreads();
        if (i + 1 < nit) load_stage(s ^ 1, (i + 1) * 32);

        uint32_t base = sb + s * STG;
#pragma unroll
        for (int kh = 0; kh < 2; kh++) {
            uint32_t colB = (uint32_t)((kh * 16 + lc * 8) * 2);
            uint32_t ra_h[2][4], ra_l[2][4], rb_h[NP][4], rb_l[NP][4];
#pragma unroll
            for (int mt = 0; mt < 2; mt++)
                ldmx4(ra_h[mt], base + (uint32_t)((wm * 32 + mt * 16 + lr) * ROWP) + colB);
#pragma unroll
            for (int np = 0; np < NP; np++)
                ldmx4(rb_h[np], base + 2 * TILA +
                      (uint32_t)((wn * NP * 16 + np * 16 + lr) * ROWP) + colB);
#pragma unroll
            for (int mt = 0; mt < 2; mt++)
#pragma unroll
                for (int np = 0; np < NP; np++) {
                    mma_bf16(acc[mt][2 * np],     ra_h[mt], rb_h[np][0], rb_h[np][2]);
                    mma_bf16(acc[mt][2 * np + 1], ra_h[mt], rb_h[np][1], rb_h[np][3]);
                }
#pragma unroll
            for (int mt = 0; mt < 2; mt++)
                ldmx4(ra_l[mt], base + TILA +
                      (uint32_t)((wm * 32 + mt * 16 + lr) * ROWP) + colB);
#pragma unroll
            for (int mt = 0; mt < 2; mt++)
#pragma unroll
                for (int np = 0; np < NP; np++) {
                    mma_bf16(acc[mt][2 * np],     ra_l[mt], rb_h[np][0], rb_h[np][2]);
                    mma_bf16(acc[mt][2 * np + 1], ra_l[mt], rb_h[np][1], rb_h[np][3]);
                }
#pragma unroll
            for (int np = 0; np < NP; np++)
                ldmx4(rb_l[np], base + 2 * TILA + TILB +
                      (uint32_t)((wn * NP * 16 + np * 16 + lr) * ROWP) + colB);
#pragma unroll
            for (int mt = 0; mt < 2; mt++)
#pragma unroll
                for (int np = 0; np < NP; np++) {
                    mma_bf16(acc[mt][2 * np],     ra_h[mt], rb_l[np][0], rb_l[np][2]);
                    mma_bf16(acc[mt][2 * np + 1], ra_h[mt], rb_l[np][1], rb_l[np][3]);
                }
        }
        __syncthreads();
    }

    int qr = lane >> 2, qc = lane & 3;
#pragma unroll
    for (int mt = 0; mt < 2; mt++) {
        int r0 = m0 + wm * 32 + mt * 16 + qr;
#pragma unroll
        for (int nt = 0; nt < 2 * NP; nt++) {
            int cidx = n0 + wn * NP * 16 + nt * 8 + qc * 2;
            float b0 = __ldg(bias + cidx), b1 = __ldg(bias + cidx + 1);
            float v00 = acc[mt][nt][0] + b0, v01 = acc[mt][nt][1] + b1;
            float v10 = acc[mt][nt][2] + b0, v11 = acc[mt][nt][3] + b1;
            if (RELU) {
                v00 = fmaxf(v00, 0.f); v01 = fmaxf(v01, 0.f);
                v10 = fmaxf(v10, 0.f); v11 = fmaxf(v11, 0.f);
            }
            *(__half2*)(O + (size_t)r0 * ldO + cidx) = __floats2half2_rn(v00, v01);
            *(__half2*)(O + (size_t)(r0 + 8) * ldO + cidx) = __floats2half2_rn(v10, v11);
        }
    }
}

// ===== fp16 logit GEMM (R10 config) + fused per-row stat accumulation =========
// CTA 128x128, 256 thr, BK=32, 4-stage, 2 CTAs/SM. Stats: max(enc-uint atomicMax)
// and {se, sl, sum, sq} atomicAdd per row; no max-subtraction (logits are small).
#define FTILA (128 * ROWP)               // 10240
#define FSTG (2 * FTILA)                 // 20480
#define FSMEM (4 * FSTG)                 // 81920

__global__ __launch_bounds__(256, 2) void k_mmaf16(
    const __half* __restrict__ A, const __half* __restrict__ B,
    const float* __restrict__ bias, float* __restrict__ C, int Kdim, int ldC,
    unsigned* __restrict__ rmx, float* __restrict__ rsm)
{
    extern __shared__ char smem[];
    uint32_t sb = smem_u32(smem);
    int tid = threadIdx.x;
    int w = tid >> 5, lane = tid & 31;
    int wm = w & 3, wn = w >> 2;            // warp tile 32x64
    int m0 = blockIdx.x * 128;
    int n0 = blockIdx.y * 128;
    int nit = Kdim / 32;

    float acc[2][8][4];
#pragma unroll
    for (int a = 0; a < 2; a++)
#pragma unroll
        for (int b = 0; b < 8; b++)
#pragma unroll
            for (int c = 0; c < 4; c++) acc[a][b][c] = 0.f;

    auto load_stage = [&](int s, int k0) {
        uint32_t base = sb + s * FSTG;
#pragma unroll
        for (int t = 0; t < 2; t++) {
            int idx = tid + t * 256;
            int r = idx >> 2, c = idx & 3;
            uint32_t so = (uint32_t)(r * ROWP + c * 16);
            cp16(base + so, A + (size_t)(m0 + r) * Kdim + k0 + c * 8);
            cp16(base + FTILA + so, B + (size_t)(n0 + r) * Kdim + k0 + c * 8);
        }
        CP_COMMIT();
    };

    load_stage(0, 0);
    if (nit > 1) load_stage(1, 32);
    if (nit > 2) load_stage(2, 64);

    int lr = lane & 15, lc = lane >> 4;
#pragma unroll 1
    for (int i = 0; i < nit; i++) {
        // exact tail waits: ensure group i complete
        if (i + 3 <= nit) { CP_WAIT(2); }
        else if (i + 2 == nit) { CP_WAIT(1); }
        else { CP_WAIT(0); }
        __syncthreads();
        if (i + 3 < nit) load_stage((i + 3) & 3, (i + 3) * 32);

        uint32_t base = sb + (i & 3) * FSTG;
#pragma unroll
        for (int kh = 0; kh < 2; kh++) {
            uint32_t colB = (uint32_t)((kh * 16 + lc * 8) * 2);
            uint32_t ra[2][4], rb[4][4];
#pragma unroll
            for (int mt = 0; mt < 2; mt++)
                ldmx4(ra[mt], base + (uint32_t)((wm * 32 + mt * 16 + lr) * ROWP) + colB);
#pragma unroll
            for (int np = 0; np < 4; np++)
                ldmx4(rb[np], base + FTILA +
                      (uint32_t)((wn * 64 + np * 16 + lr) * ROWP) + colB);
#pragma unroll
            for (int mt = 0; mt < 2; mt++)
#pragma unroll
                for (int np = 0; np < 4; np++) {
                    mma_f16(acc[mt][2 * np],     ra[mt], rb[np][0], rb[np][2]);
                    mma_f16(acc[mt][2 * np + 1], ra[mt], rb[np][1], rb[np][3]);
                }
        }
        // no bottom barrier: next iter's top barrier orders laggards vs the
        // stage overwritten then (4-deep ring)
    }

    // epilogue: store + per-thread stats for 4 rows (mt x {r0, r0+8})
    int qr = lane >> 2, qc = lane & 3;
    float pmx[2][2], pse[2][2], psl[2][2], psum[2][2], psq[2][2];
#pragma unroll
    for (int mt = 0; mt < 2; mt++)
#pragma unroll
        for (int hh = 0; hh < 2; hh++) {
            pmx[mt][hh] = -INFINITY; pse[mt][hh] = 0.f; psl[mt][hh] = 0.f;
            psum[mt][hh] = 0.f; psq[mt][hh] = 0.f;
        }
#pragma unroll
    for (int mt = 0; mt < 2; mt++) {
        int r0 = m0 + wm * 32 + mt * 16 + qr;
#pragma unroll
        for (int nt = 0; nt < 8; nt++) {
            int cidx = n0 + wn * 64 + nt * 8 + qc * 2;
            float b0 = __ldg(bias + cidx), b1 = __ldg(bias + cidx + 1);
            float v00 = acc[mt][nt][0] + b0, v01 = acc[mt][nt][1] + b1;
            float v10 = acc[mt][nt][2] + b0, v11 = acc[mt][nt][3] + b1;
            *(float2*)(C + (size_t)r0 * ldC + cidx) = make_float2(v00, v01);
            *(float2*)(C + (size_t)(r0 + 8) * ldC + cidx) = make_float2(v10, v11);
            float e;
            pmx[mt][0] = fmaxf(pmx[mt][0], fmaxf(v00, v01));
            e = __expf(v00); pse[mt][0] += e; psl[mt][0] += e * v00;
            e = __expf(v01); pse[mt][0] += e; psl[mt][0] += e * v01;
            psum[mt][0] += v00 + v01; psq[mt][0] += v00 * v00 + v01 * v01;
            pmx[mt][1] = fmaxf(pmx[mt][1], fmaxf(v10, v11));
            e = __expf(v10); pse[mt][1] += e; psl[mt][1] += e * v10;
            e = __expf(v11); pse[mt][1] += e; psl[mt][1] += e * v11;
            psum[mt][1] += v10 + v11; psq[mt][1] += v10 * v10 + v11 * v11;
        }
    }
    // reduce across the 4 lanes (qc) that share each row
#pragma unroll
    for (int o = 1; o <= 2; o <<= 1) {
#pragma unroll
        for (int mt = 0; mt < 2; mt++)
#pragma unroll
            for (int hh = 0; hh < 2; hh++) {
                pmx[mt][hh]  = fmaxf(pmx[mt][hh], __shfl_xor_sync(0xffffffffu, pmx[mt][hh], o));
                pse[mt][hh]  += __shfl_xor_sync(0xffffffffu, pse[mt][hh], o);
                psl[mt][hh]  += __shfl_xor_sync(0xffffffffu, psl[mt][hh], o);
                psum[mt][hh] += __shfl_xor_sync(0xffffffffu, psum[mt][hh], o);
                psq[mt][hh]  += __shfl_xor_sync(0xffffffffu, psq[mt][hh], o);
            }
    }
    if (qc == 0) {
#pragma unroll
        for (int mt = 0; mt < 2; mt++)
#pragma unroll
            for (int hh = 0; hh < 2; hh++) {
                int r = m0 + wm * 32 + mt * 16 + qr + hh * 8;
                atomicMax(rmx + r, enc_max(pmx[mt][hh]));
                atomicAdd(rsm + r * 4 + 0, pse[mt][hh]);
                atomicAdd(rsm + r * 4 + 1, psl[mt][hh]);
                atomicAdd(rsm + r * 4 + 2, psum[mt][hh]);
                atomicAdd(rsm + r * 4 + 3, psq[mt][hh]);
            }
    }
}

// ------------- gate from fused accumulators + mix (in place on out) -----------
__global__ void k_mix(float* __restrict__ out,
                      const float* __restrict__ gw, const float* __restrict__ gb)
{
    int row = blockIdx.x;
    float seA = g_smA[row * 4 + 0], slA = g_smA[row * 4 + 1];
    float smA = g_smA[row * 4 + 2], sqA = g_smA[row * 4 + 3];
    float seB = g_smB[row * 4 + 0], slB = g_smB[row * 4 + 1];
    float smB = g_smB[row * 4 + 2], sqB = g_smB[row * 4 + 3];
    float mxA = dec_max(g_mxA[row]);
    float mxB = dec_max(g_mxB[row]);
    float entA = logf(seA) - slA / seA;
    float entB = logf(seB) - slB / seB;
    float mA = smA * (1.f / VV), mB = smB * (1.f / VV);
    float varA = sqA * (1.f / VV) - mA * mA;
    float varB = sqB * (1.f / VV) - mB * mB;
    float z = __ldg(gb);
    z = fmaf(entA, __ldg(gw + 0), z);
    z = fmaf(mxA,  __ldg(gw + 1), z);
    z = fmaf(varA, __ldg(gw + 2), z);
    z = fmaf(entB, __ldg(gw + 3), z);
    z = fmaf(mxB,  __ldg(gw + 4), z);
    z = fmaf(varB, __ldg(gw + 5), z);
    float g = 1.f / (1.f + expf(-z));

    float4* po = (float4*)(out + (size_t)row * VV);
    const float4* pc = (const float4*)(g_loc + (size_t)row * VV);
    for (int i = threadIdx.x; i < VV / 4; i += 256) {
        float4 a = po[i];
        float4 c = pc[i];
        float4 r;
        r.x = fmaf(g, a.x - c.x, c.x);
        r.y = fmaf(g, a.y - c.y, c.y);
        r.z = fmaf(g, a.z - c.z, c.z);
        r.w = fmaf(g, a.w - c.w, c.w);
        po[i] = r;
    }
}

// ---------------- launcher (two-stream overlapped graph) ----------------------
extern "C" void kernel_launch(void* const* d_in, const int* in_sizes, int n_in,
                              void* d_out, int out_size)
{
    const int*   chars   = (const int*)  d_in[0];
    const float* emb     = (const float*)d_in[1];
    const float* in_proj = (const float*)d_in[2];
    const float* decays  = (const float*)d_in[3];
    const float* lin_W1  = (const float*)d_in[4];
    const float* lin_b1  = (const float*)d_in[5];
    const float* lin_W2  = (const float*)d_in[6];
    const float* lin_b2  = (const float*)d_in[7];
    const float* loc_W1  = (const float*)d_in[8];
    const float* loc_b1  = (const float*)d_in[9];
    const float* loc_W2  = (const float*)d_in[10];
    const float* loc_b2  = (const float*)d_in[11];
    const float* gate_W  = (const float*)d_in[12];
    const float* gate_b  = (const float*)d_in[13];
    float* out = (float*)d_out;

    float *px, *pdrive, *ploc, *psmA, *psmB;
    unsigned *pmxA, *pmxB;
    __nv_bfloat16 *pzh, *pzl, *psh, *psl;
    __nv_bfloat16 *pw1lh, *pw1ll, *pw1ch, *pw1cl;
    __half *pha, *phb, *pwl, *pwc;
    cudaGetSymbolAddress((void**)&px,     g_x);
    cudaGetSymbolAddress((void**)&pdrive, g_drive);
    cudaGetSymbolAddress((void**)&ploc,   g_loc);
    cudaGetSymbolAddress((void**)&pmxA,   g_mxA);
    cudaGetSymbolAddress((void**)&pmxB,   g_mxB);
    cudaGetSymbolAddress((void**)&psmA,   g_smA);
    cudaGetSymbolAddress((void**)&psmB,   g_smB);
    cudaGetSymbolAddress((void**)&pzh,    g_zh);
    cudaGetSymbolAddress((void**)&pzl,    g_zl);
    cudaGetSymbolAddress((void**)&psh,    g_sh);
    cudaGetSymbolAddress((void**)&psl,    g_sl);
    cudaGetSymbolAddress((void**)&pha,    g_ha16);
    cudaGetSymbolAddress((void**)&phb,    g_hb16);
    cudaGetSymbolAddress((void**)&pwl,    g_w16l);
    cudaGetSymbolAddress((void**)&pwc,    g_w16c);
    cudaGetSymbolAddress((void**)&pw1lh,  g_w1l_h);
    cudaGetSymbolAddress((void**)&pw1ll,  g_w1l_l);
    cudaGetSymbolAddress((void**)&pw1ch,  g_w1c_h);
    cudaGetSymbolAddress((void**)&pw1cl,  g_w1c_l);

    constexpr int SM64 = 2 * (2 * 64 * ROWP + 2 * TILB);   // 61440
    static cudaStream_t s1 = nullptr;
    static cudaEvent_t e0 = nullptr, e1 = nullptr;
    static bool init_done = false;
    if (!init_done) {
        cudaFuncSetAttribute(k_mma3<64, true>, cudaFuncAttributeMaxDynamicSharedMemorySize, SM64);
        cudaFuncSetAttribute(k_mmaf16, cudaFuncAttributeMaxDynamicSharedMemorySize, FSMEM);
        cudaStreamCreateWithFlags(&s1, cudaStreamNonBlocking);
        cudaEventCreateWithFlags(&e0, cudaEventDisableTiming);
        cudaEventCreateWithFlags(&e1, cudaEventDisableTiming);
        init_done = true;
    }

    // head (s0): zero stat accumulators, then embed
    k_zero<<<RR * 4 / 256, 256>>>();
    k_embed<<<RR, 64>>>(chars, emb);
    cudaEventRecord(e0, 0);
    cudaStreamWaitEvent(s1, e0, 0);

    // ---- s1: loc path ----
    k_stack<<<dim3(RR, WW), 64, 0, s1>>>();
    k_wsplitT<<<dim3(HH / 32, SK / 32), dim3(32, 8), 0, s1>>>(loc_W1, pw1ch, pw1cl, SK, HH);
    k_mma3<64, true><<<dim3(RR / 64, HH / 128), 256, SM64, s1>>>(
        psh, psl, pw1ch, pw1cl, loc_b1, phb, SK, HH);
    k_wconvT<<<dim3(VV / 32, HH / 32), dim3(32, 8), 0, s1>>>(loc_W2, pwc, HH, VV);
    k_mmaf16<<<dim3(RR / 128, VV / 128), 256, FSMEM, s1>>>(
        phb, pwc, loc_b2, ploc, HH, VV, pmxB, psmB);
    cudaEventRecord(e1, s1);

    // ---- s0: lin path ----
    k_gemm<<<dim3(MM / GBN, RR / GBM), 256>>>(px, in_proj, pdrive, MM, EE);
    k_scan<<<2, 256>>>(decays);
    k_wsplitT<<<dim3(HH / 32, ZK / 32), dim3(32, 8)>>>(lin_W1, pw1lh, pw1ll, ZK, HH);
    k_mma3<64, true><<<dim3(RR / 64, HH / 128), 256, SM64>>>(
        pzh, pzl, pw1lh, pw1ll, lin_b1, pha, ZK, HH);
    k_wconvT<<<dim3(VV / 32, HH / 32), dim3(32, 8)>>>(lin_W2, pwl, HH, VV);
    k_mmaf16<<<dim3(RR / 128, VV / 128), 256, FSMEM>>>(
        pha, pwl, lin_b2, out, HH, VV, pmxA, psmA);

    // ---- join + mix (s0) ----
    cudaStreamWaitEvent(0, e1, 0);
    k_mix<<<RR, 256>>>(out, gate_W, gate_b);
}

// round 13
// speedup vs baseline: 1.2456x; 1.0616x over previous
#include <cuda_runtime.h>
#include <cuda_bf16.h>
#include <cuda_fp16.h>
#include <math.h>
#include <stdint.h>

// Problem dims (fixed)
#define BB 2
#define TT 1024
#define RR 2048          // B*T rows
#define EE 256
#define MM 256
#define HH 1024
#define VV 32000
#define WW 8
#define ZK 512           // M+E
#define SK 2048          // W*E

// ================= PTX helpers (arch-agnostic only!) ==========================
__device__ __forceinline__ uint32_t smem_u32(const void* p) {
    uint32_t a;
    asm("{ .reg .u64 t; cvta.to.shared.u64 t, %1; cvt.u32.u64 %0, t; }" : "=r"(a) : "l"(p));
    return a;
}
__device__ __forceinline__ void cp16(uint32_t saddr, const void* g) {
    asm volatile("cp.async.cg.shared.global [%0], [%1], 16;\n" :: "r"(saddr), "l"(g));
}
#define CP_COMMIT() asm volatile("cp.async.commit_group;\n" ::: "memory")
#define CP_WAIT(n)  asm volatile("cp.async.wait_group %0;\n" :: "n"(n) : "memory")

__device__ __forceinline__ void ldmx4(uint32_t* r, uint32_t addr) {
    asm volatile("ldmatrix.sync.aligned.m8n8.x4.shared.b16 {%0,%1,%2,%3}, [%4];"
        : "=r"(r[0]), "=r"(r[1]), "=r"(r[2]), "=r"(r[3]) : "r"(addr));
}
__device__ __forceinline__ void mma_f16(float* c, const uint32_t* a,
                                        uint32_t b0, uint32_t b1) {
    asm volatile("mma.sync.aligned.m16n8k16.row.col.f32.f16.f16.f32 "
        "{%0,%1,%2,%3}, {%4,%5,%6,%7}, {%8,%9}, {%0,%1,%2,%3};"
        : "+f"(c[0]), "+f"(c[1]), "+f"(c[2]), "+f"(c[3])
        : "r"(a[0]), "r"(a[1]), "r"(a[2]), "r"(a[3]), "r"(b0), "r"(b1));
}
// ordered-uint encoding for float atomicMax
__device__ __forceinline__ unsigned enc_max(float x) {
    unsigned b = __float_as_uint(x);
    return (b >> 31) ? ~b : (b | 0x80000000u);
}
__device__ __forceinline__ float dec_max(unsigned e) {
    return (e & 0x80000000u) ? __uint_as_float(e & 0x7fffffffu) : __uint_as_float(~e);
}

// ---------------- scratch (device globals; no allocation allowed) -------------
__device__ float g_x[RR * EE];
__device__ float g_drive[RR * MM];
__device__ float g_loc[(size_t)RR * VV];
// fused logit-stat accumulators: per row {se, sl, sum, sq} + encoded max
__device__ unsigned g_mxA[RR];
__device__ unsigned g_mxB[RR];
__device__ float g_smA[RR * 4];
__device__ float g_smB[RR * 4];
// fp16 activations
__device__ __half g_z16[RR * ZK];               // [states | x]
__device__ __half g_s16[RR * SK];               // windowed stack
__device__ __half g_ha16[RR * HH];              // lin hidden
__device__ __half g_hb16[RR * HH];              // loc hidden
// fp16 transposed weights [N,K]
__device__ __half g_w16l[(size_t)VV * HH];      // lin_W2^T
__device__ __half g_w16c[(size_t)VV * HH];      // loc_W2^T
__device__ __half g_w1l16[HH * ZK];             // lin_W1^T
__device__ __half g_w1c16[(size_t)HH * SK];     // loc_W1^T

// -------- zero the stat accumulators (graph-replay safe) ----------------------
__global__ void k_zero() {
    int i = blockIdx.x * 256 + threadIdx.x;
    if (i < RR) { g_mxA[i] = 0x007fffffu; g_mxB[i] = 0x007fffffu; }  // enc(-inf)
    if (i < RR * 4) { g_smA[i] = 0.f; g_smB[i] = 0.f; }
}

// -------- embed: x fp32 (for drive/stack) + z[:,256:512] fp16 -----------------
__global__ void k_embed(const int* __restrict__ chars, const float* __restrict__ emb) {
    int row = blockIdx.x;
    int c = chars[row];
    const float4* src = (const float4*)(emb + (size_t)c * EE);
    float4* dx = (float4*)(g_x + (size_t)row * EE);
    int i = threadIdx.x;
    float4 v = src[i];
    dx[i] = v;
    __half2* dz = (__half2*)(g_z16 + (size_t)row * ZK + MM + i * 4);
    dz[0] = __floats2half2_rn(v.x, v.y);
    dz[1] = __floats2half2_rn(v.z, v.w);
}

// -------- decay scan -> z[:,0:256] fp16 ---------------------------------------
__global__ void k_scan(const float* __restrict__ decays) {
    int idx = blockIdx.x * blockDim.x + threadIdx.x;
    if (idx >= BB * MM) return;
    int b = idx >> 8;
    int m = idx & 255;
    float d = decays[m];
    float s = 0.f;
    const float* dr = g_drive + (size_t)b * TT * MM + m;
    __half* z = g_z16 + (size_t)b * TT * ZK + m;
    for (int t = 0; t < TT; t++) {
        s = fmaf(d, s, dr[(size_t)t * MM]);
        z[(size_t)t * ZK] = __float2half_rn(s);
    }
}

// -------- windowed stack -> fp16 ----------------------------------------------
__global__ void k_stack() {
    int row = blockIdx.x;
    int o = blockIdx.y;
    int t = row & (TT - 1);
    __half2* d = (__half2*)(g_s16 + (size_t)row * SK + o * EE + threadIdx.x * 4);
    if (t - o >= 0) {
        float4 v = ((const float4*)(g_x + (size_t)(row - o) * EE))[threadIdx.x];
        d[0] = __floats2half2_rn(v.x, v.y);
        d[1] = __floats2half2_rn(v.z, v.w);
    } else {
        __half2 zz = __floats2half2_rn(0.f, 0.f);
        d[0] = zz; d[1] = zz;
    }
}

// ---------------- SIMT fp32 GEMM (drive only) ---------------------------------
#define GBM 128
#define GBN 128
#define GBK 16
__global__ __launch_bounds__(256, 2) void k_gemm(
    const float* __restrict__ A, const float* __restrict__ B,
    float* __restrict__ C, int Ndim, int Kdim)
{
    __shared__ float As[GBK][GBM + 4];
    __shared__ float Bs[GBK][GBN + 4];
    int tid = threadIdx.x;
    int m0 = blockIdx.y * GBM;
    int n0 = blockIdx.x * GBN;
    int ty = tid >> 4, tx = tid & 15;
    float acc[8][8];
#pragma unroll
    for (int i = 0; i < 8; i++)
#pragma unroll
        for (int j = 0; j < 8; j++) acc[i][j] = 0.f;
    for (int k0 = 0; k0 < Kdim; k0 += GBK) {
#pragma unroll
        for (int r = 0; r < 2; r++) {
            int idx = tid + r * 256;
            int ar = idx >> 2, ac4 = idx & 3;
            float4 va = *(const float4*)(A + (size_t)(m0 + ar) * Kdim + k0 + ac4 * 4);
            As[ac4 * 4 + 0][ar] = va.x;
            As[ac4 * 4 + 1][ar] = va.y;
            As[ac4 * 4 + 2][ar] = va.z;
            As[ac4 * 4 + 3][ar] = va.w;
            int br = idx >> 5, bc4 = idx & 31;
            float4 vb = *(const float4*)(B + (size_t)(k0 + br) * Ndim + n0 + bc4 * 4);
            *(float4*)&Bs[br][bc4 * 4] = vb;
        }
        __syncthreads();
#pragma unroll
        for (int kk = 0; kk < GBK; kk++) {
            float a[8], b[8];
            *(float4*)&a[0] = *(const float4*)&As[kk][ty * 8];
            *(float4*)&a[4] = *(const float4*)&As[kk][ty * 8 + 4];
            *(float4*)&b[0] = *(const float4*)&Bs[kk][tx * 8];
            *(float4*)&b[4] = *(const float4*)&Bs[kk][tx * 8 + 4];
#pragma unroll
            for (int i = 0; i < 8; i++)
#pragma unroll
                for (int j = 0; j < 8; j++)
                    acc[i][j] = fmaf(a[i], b[j], acc[i][j]);
        }
        __syncthreads();
    }
#pragma unroll
    for (int i = 0; i < 8; i++) {
        int m = m0 + ty * 8 + i;
#pragma unroll
        for (int j = 0; j < 8; j += 4) {
            int n = n0 + tx * 8 + j;
            float4 v;
            v.x = acc[i][j + 0]; v.y = acc[i][j + 1];
            v.z = acc[i][j + 2]; v.w = acc[i][j + 3];
            *(float4*)(C + (size_t)m * Ndim + n) = v;
        }
    }
}

// ---------- transpose + convert W[Krows,Ncols] -> Wt[N,K] fp16 ----------------
__global__ void k_wconvT(const float* __restrict__ Wsrc,
                         __half* __restrict__ T, int Krows, int Ncols) {
    __shared__ float tile[32][33];
    int n0 = blockIdx.x * 32;
    int k0 = blockIdx.y * 32;
    int tx = threadIdx.x, ty = threadIdx.y;
#pragma unroll
    for (int r = 0; r < 32; r += 8)
        tile[ty + r][tx] = Wsrc[(size_t)(k0 + ty + r) * Ncols + n0 + tx];
    __syncthreads();
#pragma unroll
    for (int r = 0; r < 32; r += 8)
        T[(size_t)(n0 + ty + r) * Krows + k0 + tx] = __float2half_rn(tile[tx][ty + r]);
}

// ===== unified fp16 GEMM: CTA 128x128, 256 thr, BK=32, 4-stage, 2 CTAs/SM =====
// C[M,N] = act(A[M,K] @ B[N,K]^T + bias); optional fp16 out; optional fused
// per-row softmax-stat accumulation (max/se/sl/sum/sq) via atomics.
#define ROWP 80
#define FTILA (128 * ROWP)               // 10240
#define FSTG (2 * FTILA)                 // 20480
#define FSMEM (4 * FSTG)                 // 81920

template<bool RELU, bool HALFOUT, bool STATS>
__global__ __launch_bounds__(256, 2) void k_mf16(
    const __half* __restrict__ A, const __half* __restrict__ B,
    const float* __restrict__ bias, float* __restrict__ C,
    __half* __restrict__ Ch, int Kdim, int ldC,
    unsigned* __restrict__ rmx, float* __restrict__ rsm)
{
    extern __shared__ char smem[];
    uint32_t sb = smem_u32(smem);
    int tid = threadIdx.x;
    int w = tid >> 5, lane = tid & 31;
    int wm = w & 3, wn = w >> 2;            // warp tile 32x64
    int m0 = blockIdx.x * 128;
    int n0 = blockIdx.y * 128;
    int nit = Kdim / 32;

    float acc[2][8][4];
#pragma unroll
    for (int a = 0; a < 2; a++)
#pragma unroll
        for (int b = 0; b < 8; b++)
#pragma unroll
            for (int c = 0; c < 4; c++) acc[a][b][c] = 0.f;

    auto load_stage = [&](int s, int k0) {
        uint32_t base = sb + s * FSTG;
#pragma unroll
        for (int t = 0; t < 2; t++) {
            int idx = tid + t * 256;
            int r = idx >> 2, c = idx & 3;
            uint32_t so = (uint32_t)(r * ROWP + c * 16);
            cp16(base + so, A + (size_t)(m0 + r) * Kdim + k0 + c * 8);
            cp16(base + FTILA + so, B + (size_t)(n0 + r) * Kdim + k0 + c * 8);
        }
        CP_COMMIT();
    };

    load_stage(0, 0);
    if (nit > 1) load_stage(1, 32);
    if (nit > 2) load_stage(2, 64);

    int lr = lane & 15, lc = lane >> 4;
#pragma unroll 1
    for (int i = 0; i < nit; i++) {
        // exact tail waits: ensure group i complete
        if (i + 3 <= nit) { CP_WAIT(2); }
        else if (i + 2 == nit) { CP_WAIT(1); }
        else { CP_WAIT(0); }
        __syncthreads();
        if (i + 3 < nit) load_stage((i + 3) & 3, (i + 3) * 32);

        uint32_t base = sb + (i & 3) * FSTG;
#pragma unroll
        for (int kh = 0; kh < 2; kh++) {
            uint32_t colB = (uint32_t)((kh * 16 + lc * 8) * 2);
            uint32_t ra[2][4], rb[4][4];
#pragma unroll
            for (int mt = 0; mt < 2; mt++)
                ldmx4(ra[mt], base + (uint32_t)((wm * 32 + mt * 16 + lr) * ROWP) + colB);
#pragma unroll
            for (int np = 0; np < 4; np++)
                ldmx4(rb[np], base + FTILA +
                      (uint32_t)((wn * 64 + np * 16 + lr) * ROWP) + colB);
#pragma unroll
            for (int mt = 0; mt < 2; mt++)
#pragma unroll
                for (int np = 0; np < 4; np++) {
                    mma_f16(acc[mt][2 * np],     ra[mt], rb[np][0], rb[np][2]);
                    mma_f16(acc[mt][2 * np + 1], ra[mt], rb[np][1], rb[np][3]);
                }
        }
        // no bottom barrier: next iter's top barrier orders laggards vs the
        // stage overwritten then (4-deep ring)
    }

    int qr = lane >> 2, qc = lane & 3;
    float pmx[2][2], pse[2][2], psl[2][2], psum[2][2], psq[2][2];
    if (STATS) {
#pragma unroll
        for (int mt = 0; mt < 2; mt++)
#pragma unroll
            for (int hh = 0; hh < 2; hh++) {
                pmx[mt][hh] = -INFINITY; pse[mt][hh] = 0.f; psl[mt][hh] = 0.f;
                psum[mt][hh] = 0.f; psq[mt][hh] = 0.f;
            }
    }
#pragma unroll
    for (int mt = 0; mt < 2; mt++) {
        int r0 = m0 + wm * 32 + mt * 16 + qr;
#pragma unroll
        for (int nt = 0; nt < 8; nt++) {
            int cidx = n0 + wn * 64 + nt * 8 + qc * 2;
            float b0 = __ldg(bias + cidx), b1 = __ldg(bias + cidx + 1);
            float v00 = acc[mt][nt][0] + b0, v01 = acc[mt][nt][1] + b1;
            float v10 = acc[mt][nt][2] + b0, v11 = acc[mt][nt][3] + b1;
            if (RELU) {
                v00 = fmaxf(v00, 0.f); v01 = fmaxf(v01, 0.f);
                v10 = fmaxf(v10, 0.f); v11 = fmaxf(v11, 0.f);
            }
            if (HALFOUT) {
                *(__half2*)(Ch + (size_t)r0 * ldC + cidx) = __floats2half2_rn(v00, v01);
                *(__half2*)(Ch + (size_t)(r0 + 8) * ldC + cidx) = __floats2half2_rn(v10, v11);
            } else {
                *(float2*)(C + (size_t)r0 * ldC + cidx) = make_float2(v00, v01);
                *(float2*)(C + (size_t)(r0 + 8) * ldC + cidx) = make_float2(v10, v11);
            }
            if (STATS) {
                float e;
                pmx[mt][0] = fmaxf(pmx[mt][0], fmaxf(v00, v01));
                e = __expf(v00); pse[mt][0] += e; psl[mt][0] += e * v00;
                e = __expf(v01); pse[mt][0] += e; psl[mt][0] += e * v01;
                psum[mt][0] += v00 + v01; psq[mt][0] += v00 * v00 + v01 * v01;
                pmx[mt][1] = fmaxf(pmx[mt][1], fmaxf(v10, v11));
                e = __expf(v10); pse[mt][1] += e; psl[mt][1] += e * v10;
                e = __expf(v11); pse[mt][1] += e; psl[mt][1] += e * v11;
                psum[mt][1] += v10 + v11; psq[mt][1] += v10 * v10 + v11 * v11;
            }
        }
    }
    if (STATS) {
#pragma unroll
        for (int o = 1; o <= 2; o <<= 1) {
#pragma unroll
            for (int mt = 0; mt < 2; mt++)
#pragma unroll
                for (int hh = 0; hh < 2; hh++) {
                    pmx[mt][hh]  = fmaxf(pmx[mt][hh], __shfl_xor_sync(0xffffffffu, pmx[mt][hh], o));
                    pse[mt][hh]  += __shfl_xor_sync(0xffffffffu, pse[mt][hh], o);
                    psl[mt][hh]  += __shfl_xor_sync(0xffffffffu, psl[mt][hh], o);
                    psum[mt][hh] += __shfl_xor_sync(0xffffffffu, psum[mt][hh], o);
                    psq[mt][hh]  += __shfl_xor_sync(0xffffffffu, psq[mt][hh], o);
                }
        }
        if (qc == 0) {
#pragma unroll
            for (int mt = 0; mt < 2; mt++)
#pragma unroll
                for (int hh = 0; hh < 2; hh++) {
                    int r = m0 + wm * 32 + mt * 16 + qr + hh * 8;
                    atomicMax(rmx + r, enc_max(pmx[mt][hh]));
                    atomicAdd(rsm + r * 4 + 0, pse[mt][hh]);
                    atomicAdd(rsm + r * 4 + 1, psl[mt][hh]);
                    atomicAdd(rsm + r * 4 + 2, psum[mt][hh]);
                    atomicAdd(rsm + r * 4 + 3, psq[mt][hh]);
                }
        }
    }
}

// ------------- gate from fused accumulators + mix (in place on out) -----------
__global__ void k_mix(float* __restrict__ out,
                      const float* __restrict__ gw, const float* __restrict__ gb)
{
    int row = blockIdx.x;
    float seA = g_smA[row * 4 + 0], slA = g_smA[row * 4 + 1];
    float smA = g_smA[row * 4 + 2], sqA = g_smA[row * 4 + 3];
    float seB = g_smB[row * 4 + 0], slB = g_smB[row * 4 + 1];
    float smB = g_smB[row * 4 + 2], sqB = g_smB[row * 4 + 3];
    float mxA = dec_max(g_mxA[row]);
    float mxB = dec_max(g_mxB[row]);
    float entA = logf(seA) - slA / seA;
    float entB = logf(seB) - slB / seB;
    float mA = smA * (1.f / VV), mB = smB * (1.f / VV);
    float varA = sqA * (1.f / VV) - mA * mA;
    float varB = sqB * (1.f / VV) - mB * mB;
    float z = __ldg(gb);
    z = fmaf(entA, __ldg(gw + 0), z);
    z = fmaf(mxA,  __ldg(gw + 1), z);
    z = fmaf(varA, __ldg(gw + 2), z);
    z = fmaf(entB, __ldg(gw + 3), z);
    z = fmaf(mxB,  __ldg(gw + 4), z);
    z = fmaf(varB, __ldg(gw + 5), z);
    float g = 1.f / (1.f + expf(-z));

    float4* po = (float4*)(out + (size_t)row * VV);
    const float4* pc = (const float4*)(g_loc + (size_t)row * VV);
    for (int i = threadIdx.x; i < VV / 4; i += 256) {
        float4 a = po[i];
        float4 c = pc[i];
        float4 r;
        r.x = fmaf(g, a.x - c.x, c.x);
        r.y = fmaf(g, a.y - c.y, c.y);
        r.z = fmaf(g, a.z - c.z, c.z);
        r.w = fmaf(g, a.w - c.w, c.w);
        po[i] = r;
    }
}

// ---------------- launcher (two-stream overlapped graph) ----------------------
extern "C" void kernel_launch(void* const* d_in, const int* in_sizes, int n_in,
                              void* d_out, int out_size)
{
    const int*   chars   = (const int*)  d_in[0];
    const float* emb     = (const float*)d_in[1];
    const float* in_proj = (const float*)d_in[2];
    const float* decays  = (const float*)d_in[3];
    const float* lin_W1  = (const float*)d_in[4];
    const float* lin_b1  = (const float*)d_in[5];
    const float* lin_W2  = (const float*)d_in[6];
    const float* lin_b2  = (const float*)d_in[7];
    const float* loc_W1  = (const float*)d_in[8];
    const float* loc_b1  = (const float*)d_in[9];
    const float* loc_W2  = (const float*)d_in[10];
    const float* loc_b2  = (const float*)d_in[11];
    const float* gate_W  = (const float*)d_in[12];
    const float* gate_b  = (const float*)d_in[13];
    float* out = (float*)d_out;

    float *px, *pdrive, *ploc, *psmA, *psmB;
    unsigned *pmxA, *pmxB;
    __half *pz, *ps, *pha, *phb, *pwl, *pwc, *pw1l, *pw1c;
    cudaGetSymbolAddress((void**)&px,     g_x);
    cudaGetSymbolAddress((void**)&pdrive, g_drive);
    cudaGetSymbolAddress((void**)&ploc,   g_loc);
    cudaGetSymbolAddress((void**)&pmxA,   g_mxA);
    cudaGetSymbolAddress((void**)&pmxB,   g_mxB);
    cudaGetSymbolAddress((void**)&psmA,   g_smA);
    cudaGetSymbolAddress((void**)&psmB,   g_smB);
    cudaGetSymbolAddress((void**)&pz,     g_z16);
    cudaGetSymbolAddress((void**)&ps,     g_s16);
    cudaGetSymbolAddress((void**)&pha,    g_ha16);
    cudaGetSymbolAddress((void**)&phb,    g_hb16);
    cudaGetSymbolAddress((void**)&pwl,    g_w16l);
    cudaGetSymbolAddress((void**)&pwc,    g_w16c);
    cudaGetSymbolAddress((void**)&pw1l,   g_w1l16);
    cudaGetSymbolAddress((void**)&pw1c,   g_w1c16);

    static cudaStream_t s1 = nullptr;
    static cudaEvent_t e0 = nullptr, e1 = nullptr;
    static bool init_done = false;
    if (!init_done) {
        cudaFuncSetAttribute(k_mf16<true, true, false>,
                             cudaFuncAttributeMaxDynamicSharedMemorySize, FSMEM);
        cudaFuncSetAttribute(k_mf16<false, false, true>,
                             cudaFuncAttributeMaxDynamicSharedMemorySize, FSMEM);
        cudaStreamCreateWithFlags(&s1, cudaStreamNonBlocking);
        cudaEventCreateWithFlags(&e0, cudaEventDisableTiming);
        cudaEventCreateWithFlags(&e1, cudaEventDisableTiming);
        init_done = true;
    }

    // head (s0): zero stat accumulators, then embed
    k_zero<<<RR * 4 / 256, 256>>>();
    k_embed<<<RR, 64>>>(chars, emb);
    cudaEventRecord(e0, 0);
    cudaStreamWaitEvent(s1, e0, 0);

    // ---- s1: loc path ----
    k_stack<<<dim3(RR, WW), 64, 0, s1>>>();
    k_wconvT<<<dim3(HH / 32, SK / 32), dim3(32, 8), 0, s1>>>(loc_W1, pw1c, SK, HH);
    k_mf16<true, true, false><<<dim3(RR / 128, HH / 128), 256, FSMEM, s1>>>(
        ps, pw1c, loc_b1, nullptr, phb, SK, HH, nullptr, nullptr);
    k_wconvT<<<dim3(VV / 32, HH / 32), dim3(32, 8), 0, s1>>>(loc_W2, pwc, HH, VV);
    k_mf16<false, false, true><<<dim3(RR / 128, VV / 128), 256, FSMEM, s1>>>(
        phb, pwc, loc_b2, ploc, nullptr, HH, VV, pmxB, psmB);
    cudaEventRecord(e1, s1);

    // ---- s0: lin path ----
    k_gemm<<<dim3(MM / GBN, RR / GBM), 256>>>(px, in_proj, pdrive, MM, EE);
    k_scan<<<2, 256>>>(decays);
    k_wconvT<<<dim3(HH / 32, ZK / 32), dim3(32, 8)>>>(lin_W1, pw1l, ZK, HH);
    k_mf16<true, true, false><<<dim3(RR / 128, HH / 128), 256, FSMEM>>>(
        pz, pw1l, lin_b1, nullptr, pha, ZK, HH, nullptr, nullptr);
    k_wconvT<<<dim3(VV / 32, HH / 32), dim3(32, 8)>>>(lin_W2, pwl, HH, VV);
    k_mf16<false, false, true><<<dim3(RR / 128, VV / 128), 256, FSMEM>>>(
        pha, pwl, lin_b2, out, nullptr, HH, VV, pmxA, psmA);

    // ---- join + mix (s0) ----
    cudaStreamWaitEvent(0, e1, 0);
    k_mix<<<RR, 256>>>(out, gate_W, gate_b);
}

// round 15
// speedup vs baseline: 1.2669x; 1.0171x over previous
#include <cuda_runtime.h>
#include <cuda_bf16.h>
#include <cuda_fp16.h>
#include <math.h>
#include <stdint.h>

// Problem dims (fixed)
#define BB 2
#define TT 1024
#define RR 2048          // B*T rows
#define EE 256
#define MM 256
#define HH 1024
#define VV 32000
#define WW 8
#define ZK 512           // M+E
#define SK 2048          // W*E

// ================= PTX helpers (arch-agnostic only!) ==========================
__device__ __forceinline__ uint32_t smem_u32(const void* p) {
    uint32_t a;
    asm("{ .reg .u64 t; cvta.to.shared.u64 t, %1; cvt.u32.u64 %0, t; }" : "=r"(a) : "l"(p));
    return a;
}
__device__ __forceinline__ void cp16(uint32_t saddr, const void* g) {
    asm volatile("cp.async.cg.shared.global [%0], [%1], 16;\n" :: "r"(saddr), "l"(g));
}
#define CP_COMMIT() asm volatile("cp.async.commit_group;\n" ::: "memory")
#define CP_WAIT(n)  asm volatile("cp.async.wait_group %0;\n" :: "n"(n) : "memory")

__device__ __forceinline__ void ldmx4(uint32_t* r, uint32_t addr) {
    asm volatile("ldmatrix.sync.aligned.m8n8.x4.shared.b16 {%0,%1,%2,%3}, [%4];"
        : "=r"(r[0]), "=r"(r[1]), "=r"(r[2]), "=r"(r[3]) : "r"(addr));
}
__device__ __forceinline__ void mma_f16(float* c, const uint32_t* a,
                                        uint32_t b0, uint32_t b1) {
    asm volatile("mma.sync.aligned.m16n8k16.row.col.f32.f16.f16.f32 "
        "{%0,%1,%2,%3}, {%4,%5,%6,%7}, {%8,%9}, {%0,%1,%2,%3};"
        : "+f"(c[0]), "+f"(c[1]), "+f"(c[2]), "+f"(c[3])
        : "r"(a[0]), "r"(a[1]), "r"(a[2]), "r"(a[3]), "r"(b0), "r"(b1));
}
// ordered-uint encoding for float atomicMax
__device__ __forceinline__ unsigned enc_max(float x) {
    unsigned b = __float_as_uint(x);
    return (b >> 31) ? ~b : (b | 0x80000000u);
}
__device__ __forceinline__ float dec_max(unsigned e) {
    return (e & 0x80000000u) ? __uint_as_float(e & 0x7fffffffu) : __uint_as_float(~e);
}

// ---------------- scratch (device globals; no allocation allowed) -------------
__device__ float g_x[RR * EE];
__device__ float g_drive[RR * MM];
__device__ __half g_loc16[(size_t)RR * VV];     // loc logits (fp16)
// fused logit-stat accumulators: per row {se, sl, sum, sq} + encoded max
__device__ unsigned g_mxA[RR];
__device__ unsigned g_mxB[RR];
__device__ float g_smA[RR * 4];
__device__ float g_smB[RR * 4];
// fp16 activations
__device__ __half g_z16[RR * ZK];               // [states | x]
__device__ __half g_s16[RR * SK];               // windowed stack
__device__ __half g_ha16[RR * HH];              // lin hidden
__device__ __half g_hb16[RR * HH];              // loc hidden
// fp16 transposed weights [N,K]
__device__ __half g_w16l[(size_t)VV * HH];      // lin_W2^T
__device__ __half g_w16c[(size_t)VV * HH];      // loc_W2^T
__device__ __half g_w1l16[HH * ZK];             // lin_W1^T
__device__ __half g_w1c16[(size_t)HH * SK];     // loc_W1^T

// -------- embed: x fp32 + z[:,256:512] fp16 + zero stat accumulators ----------
__global__ void k_embed(const int* __restrict__ chars, const float* __restrict__ emb) {
    int row = blockIdx.x;
    int i = threadIdx.x;
    if (i == 0) { g_mxA[row] = 0x007fffffu; g_mxB[row] = 0x007fffffu; }  // enc(-inf)
    if (i < 4) { g_smA[row * 4 + i] = 0.f; g_smB[row * 4 + i] = 0.f; }
    int c = chars[row];
    const float4* src = (const float4*)(emb + (size_t)c * EE);
    float4* dx = (float4*)(g_x + (size_t)row * EE);
    float4 v = src[i];
    dx[i] = v;
    __half2* dz = (__half2*)(g_z16 + (size_t)row * ZK + MM + i * 4);
    dz[0] = __floats2half2_rn(v.x, v.y);
    dz[1] = __floats2half2_rn(v.z, v.w);
}

// -------- decay scan -> z[:,0:256] fp16 ---------------------------------------
__global__ void k_scan(const float* __restrict__ decays) {
    int idx = blockIdx.x * blockDim.x + threadIdx.x;
    if (idx >= BB * MM) return;
    int b = idx >> 8;
    int m = idx & 255;
    float d = decays[m];
    float s = 0.f;
    const float* dr = g_drive + (size_t)b * TT * MM + m;
    __half* z = g_z16 + (size_t)b * TT * ZK + m;
    for (int t = 0; t < TT; t++) {
        s = fmaf(d, s, dr[(size_t)t * MM]);
        z[(size_t)t * ZK] = __float2half_rn(s);
    }
}

// -------- windowed stack -> fp16 ----------------------------------------------
__global__ void k_stack() {
    int row = blockIdx.x;
    int o = blockIdx.y;
    int t = row & (TT - 1);
    __half2* d = (__half2*)(g_s16 + (size_t)row * SK + o * EE + threadIdx.x * 4);
    if (t - o >= 0) {
        float4 v = ((const float4*)(g_x + (size_t)(row - o) * EE))[threadIdx.x];
        d[0] = __floats2half2_rn(v.x, v.y);
        d[1] = __floats2half2_rn(v.z, v.w);
    } else {
        __half2 zz = __floats2half2_rn(0.f, 0.f);
        d[0] = zz; d[1] = zz;
    }
}

// ---------------- SIMT fp32 GEMM (drive only) ---------------------------------
#define GBM 128
#define GBN 128
#define GBK 16
__global__ __launch_bounds__(256, 2) void k_gemm(
    const float* __restrict__ A, const float* __restrict__ B,
    float* __restrict__ C, int Ndim, int Kdim)
{
    __shared__ float As[GBK][GBM + 4];
    __shared__ float Bs[GBK][GBN + 4];
    int tid = threadIdx.x;
    int m0 = blockIdx.y * GBM;
    int n0 = blockIdx.x * GBN;
    int ty = tid >> 4, tx = tid & 15;
    float acc[8][8];
#pragma unroll
    for (int i = 0; i < 8; i++)
#pragma unroll
        for (int j = 0; j < 8; j++) acc[i][j] = 0.f;
    for (int k0 = 0; k0 < Kdim; k0 += GBK) {
#pragma unroll
        for (int r = 0; r < 2; r++) {
            int idx = tid + r * 256;
            int ar = idx >> 2, ac4 = idx & 3;
            float4 va = *(const float4*)(A + (size_t)(m0 + ar) * Kdim + k0 + ac4 * 4);
            As[ac4 * 4 + 0][ar] = va.x;
            As[ac4 * 4 + 1][ar] = va.y;
            As[ac4 * 4 + 2][ar] = va.z;
            As[ac4 * 4 + 3][ar] = va.w;
            int br = idx >> 5, bc4 = idx & 31;
            float4 vb = *(const float4*)(B + (size_t)(k0 + br) * Ndim + n0 + bc4 * 4);
            *(float4*)&Bs[br][bc4 * 4] = vb;
        }
        __syncthreads();
#pragma unroll
        for (int kk = 0; kk < GBK; kk++) {
            float a[8], b[8];
            *(float4*)&a[0] = *(const float4*)&As[kk][ty * 8];
            *(float4*)&a[4] = *(const float4*)&As[kk][ty * 8 + 4];
            *(float4*)&b[0] = *(const float4*)&Bs[kk][tx * 8];
            *(float4*)&b[4] = *(const float4*)&Bs[kk][tx * 8 + 4];
#pragma unroll
            for (int i = 0; i < 8; i++)
#pragma unroll
                for (int j = 0; j < 8; j++)
                    acc[i][j] = fmaf(a[i], b[j], acc[i][j]);
        }
        __syncthreads();
    }
#pragma unroll
    for (int i = 0; i < 8; i++) {
        int m = m0 + ty * 8 + i;
#pragma unroll
        for (int j = 0; j < 8; j += 4) {
            int n = n0 + tx * 8 + j;
            float4 v;
            v.x = acc[i][j + 0]; v.y = acc[i][j + 1];
            v.z = acc[i][j + 2]; v.w = acc[i][j + 3];
            *(float4*)(C + (size_t)m * Ndim + n) = v;
        }
    }
}

// ---------- transpose + convert W[Krows,Ncols] -> Wt[N,K] fp16 ----------------
__global__ void k_wconvT(const float* __restrict__ Wsrc,
                         __half* __restrict__ T, int Krows, int Ncols) {
    __shared__ float tile[32][33];
    int n0 = blockIdx.x * 32;
    int k0 = blockIdx.y * 32;
    int tx = threadIdx.x, ty = threadIdx.y;
#pragma unroll
    for (int r = 0; r < 32; r += 8)
        tile[ty + r][tx] = Wsrc[(size_t)(k0 + ty + r) * Ncols + n0 + tx];
    __syncthreads();
#pragma unroll
    for (int r = 0; r < 32; r += 8)
        T[(size_t)(n0 + ty + r) * Krows + k0 + tx] = __float2half_rn(tile[tx][ty + r]);
}

// ===== unified fp16 GEMM: CTA 128x128, 256 thr, BK=32, 4-stage, 2 CTAs/SM =====
// C = act(A[M,K] @ B[N,K]^T + bias); fp32 or fp16 out; optional fused per-row
// softmax-stat accumulation (max/se/sl/sum/sq) via atomics (stats in fp32).
#define ROWP 80
#define FTILA (128 * ROWP)               // 10240
#define FSTG (2 * FTILA)                 // 20480
#define FSMEM (4 * FSTG)                 // 81920

template<bool RELU, bool HALFOUT, bool STATS>
__global__ __launch_bounds__(256, 2) void k_mf16(
    const __half* __restrict__ A, const __half* __restrict__ B,
    const float* __restrict__ bias, float* __restrict__ C,
    __half* __restrict__ Ch, int Kdim, int ldC,
    unsigned* __restrict__ rmx, float* __restrict__ rsm)
{
    extern __shared__ char smem[];
    uint32_t sb = smem_u32(smem);
    int tid = threadIdx.x;
    int w = tid >> 5, lane = tid & 31;
    int wm = w & 3, wn = w >> 2;            // warp tile 32x64
    int m0 = blockIdx.x * 128;
    int n0 = blockIdx.y * 128;
    int nit = Kdim / 32;

    float acc[2][8][4];
#pragma unroll
    for (int a = 0; a < 2; a++)
#pragma unroll
        for (int b = 0; b < 8; b++)
#pragma unroll
            for (int c = 0; c < 4; c++) acc[a][b][c] = 0.f;

    auto load_stage = [&](int s, int k0) {
        uint32_t base = sb + s * FSTG;
#pragma unroll
        for (int t = 0; t < 2; t++) {
            int idx = tid + t * 256;
            int r = idx >> 2, c = idx & 3;
            uint32_t so = (uint32_t)(r * ROWP + c * 16);
            cp16(base + so, A + (size_t)(m0 + r) * Kdim + k0 + c * 8);
            cp16(base + FTILA + so, B + (size_t)(n0 + r) * Kdim + k0 + c * 8);
        }
        CP_COMMIT();
    };

    load_stage(0, 0);
    if (nit > 1) load_stage(1, 32);
    if (nit > 2) load_stage(2, 64);

    int lr = lane & 15, lc = lane >> 4;
#pragma unroll 1
    for (int i = 0; i < nit; i++) {
        if (i + 3 <= nit) { CP_WAIT(2); }
        else if (i + 2 == nit) { CP_WAIT(1); }
        else { CP_WAIT(0); }
        __syncthreads();
        if (i + 3 < nit) load_stage((i + 3) & 3, (i + 3) * 32);

        uint32_t base = sb + (i & 3) * FSTG;
#pragma unroll
        for (int kh = 0; kh < 2; kh++) {
            uint32_t colB = (uint32_t)((kh * 16 + lc * 8) * 2);
            uint32_t ra[2][4], rb[4][4];
#pragma unroll
            for (int mt = 0; mt < 2; mt++)
                ldmx4(ra[mt], base + (uint32_t)((wm * 32 + mt * 16 + lr) * ROWP) + colB);
#pragma unroll
            for (int np = 0; np < 4; np++)
                ldmx4(rb[np], base + FTILA +
                      (uint32_t)((wn * 64 + np * 16 + lr) * ROWP) + colB);
#pragma unroll
            for (int mt = 0; mt < 2; mt++)
#pragma unroll
                for (int np = 0; np < 4; np++) {
                    mma_f16(acc[mt][2 * np],     ra[mt], rb[np][0], rb[np][2]);
                    mma_f16(acc[mt][2 * np + 1], ra[mt], rb[np][1], rb[np][3]);
                }
        }
        // no bottom barrier: next iter's top barrier orders laggards vs the
        // stage overwritten then (4-deep ring)
    }

    int qr = lane >> 2, qc = lane & 3;
    float pmx[2][2], pse[2][2], psl[2][2], psum[2][2], psq[2][2];
    if (STATS) {
#pragma unroll
        for (int mt = 0; mt < 2; mt++)
#pragma unroll
            for (int hh = 0; hh < 2; hh++) {
                pmx[mt][hh] = -INFINITY; pse[mt][hh] = 0.f; psl[mt][hh] = 0.f;
                psum[mt][hh] = 0.f; psq[mt][hh] = 0.f;
            }
    }
#pragma unroll
    for (int mt = 0; mt < 2; mt++) {
        int r0 = m0 + wm * 32 + mt * 16 + qr;
#pragma unroll
        for (int nt = 0; nt < 8; nt++) {
            int cidx = n0 + wn * 64 + nt * 8 + qc * 2;
            float b0 = __ldg(bias + cidx), b1 = __ldg(bias + cidx + 1);
            float v00 = acc[mt][nt][0] + b0, v01 = acc[mt][nt][1] + b1;
            float v10 = acc[mt][nt][2] + b0, v11 = acc[mt][nt][3] + b1;
            if (RELU) {
                v00 = fmaxf(v00, 0.f); v01 = fmaxf(v01, 0.f);
                v10 = fmaxf(v10, 0.f); v11 = fmaxf(v11, 0.f);
            }
            if (HALFOUT) {
                *(__half2*)(Ch + (size_t)r0 * ldC + cidx) = __floats2half2_rn(v00, v01);
                *(__half2*)(Ch + (size_t)(r0 + 8) * ldC + cidx) = __floats2half2_rn(v10, v11);
            } else {
                *(float2*)(C + (size_t)r0 * ldC + cidx) = make_float2(v00, v01);
                *(float2*)(C + (size_t)(r0 + 8) * ldC + cidx) = make_float2(v10, v11);
            }
            if (STATS) {
                float e;
                pmx[mt][0] = fmaxf(pmx[mt][0], fmaxf(v00, v01));
                e = __expf(v00); pse[mt][0] += e; psl[mt][0] += e * v00;
                e = __expf(v01); pse[mt][0] += e; psl[mt][0] += e * v01;
                psum[mt][0] += v00 + v01; psq[mt][0] += v00 * v00 + v01 * v01;
                pmx[mt][1] = fmaxf(pmx[mt][1], fmaxf(v10, v11));
                e = __expf(v10); pse[mt][1] += e; psl[mt][1] += e * v10;
                e = __expf(v11); pse[mt][1] += e; psl[mt][1] += e * v11;
                psum[mt][1] += v10 + v11; psq[mt][1] += v10 * v10 + v11 * v11;
            }
        }
    }
    if (STATS) {
#pragma unroll
        for (int o = 1; o <= 2; o <<= 1) {
#pragma unroll
            for (int mt = 0; mt < 2; mt++)
#pragma unroll
                for (int hh = 0; hh < 2; hh++) {
                    pmx[mt][hh]  = fmaxf(pmx[mt][hh], __shfl_xor_sync(0xffffffffu, pmx[mt][hh], o));
                    pse[mt][hh]  += __shfl_xor_sync(0xffffffffu, pse[mt][hh], o);
                    psl[mt][hh]  += __shfl_xor_sync(0xffffffffu, psl[mt][hh], o);
                    psum[mt][hh] += __shfl_xor_sync(0xffffffffu, psum[mt][hh], o);
                    psq[mt][hh]  += __shfl_xor_sync(0xffffffffu, psq[mt][hh], o);
                }
        }
        if (qc == 0) {
#pragma unroll
            for (int mt = 0; mt < 2; mt++)
#pragma unroll
                for (int hh = 0; hh < 2; hh++) {
                    int r = m0 + wm * 32 + mt * 16 + qr + hh * 8;
                    atomicMax(rmx + r, enc_max(pmx[mt][hh]));
                    atomicAdd(rsm + r * 4 + 0, pse[mt][hh]);
                    atomicAdd(rsm + r * 4 + 1, psl[mt][hh]);
                    atomicAdd(rsm + r * 4 + 2, psum[mt][hh]);
                    atomicAdd(rsm + r * 4 + 3, psq[mt][hh]);
                }
        }
    }
}

// ------------- gate from fused accumulators + mix (loc is fp16) ---------------
__global__ void k_mix(float* __restrict__ out,
                      const float* __restrict__ gw, const float* __restrict__ gb)
{
    int row = blockIdx.x;
    float seA = g_smA[row * 4 + 0], slA = g_smA[row * 4 + 1];
    float smA = g_smA[row * 4 + 2], sqA = g_smA[row * 4 + 3];
    float seB = g_smB[row * 4 + 0], slB = g_smB[row * 4 + 1];
    float smB = g_smB[row * 4 + 2], sqB = g_smB[row * 4 + 3];
    float mxA = dec_max(g_mxA[row]);
    float mxB = dec_max(g_mxB[row]);
    float entA = logf(seA) - slA / seA;
    float entB = logf(seB) - slB / seB;
    float mA = smA * (1.f / VV), mB = smB * (1.f / VV);
    float varA = sqA * (1.f / VV) - mA * mA;
    float varB = sqB * (1.f / VV) - mB * mB;
    float z = __ldg(gb);
    z = fmaf(entA, __ldg(gw + 0), z);
    z = fmaf(mxA,  __ldg(gw + 1), z);
    z = fmaf(varA, __ldg(gw + 2), z);
    z = fmaf(entB, __ldg(gw + 3), z);
    z = fmaf(mxB,  __ldg(gw + 4), z);
    z = fmaf(varB, __ldg(gw + 5), z);
    float g = 1.f / (1.f + expf(-z));

    float4* po = (float4*)(out + (size_t)row * VV);
    const __half2* pc = (const __half2*)(g_loc16 + (size_t)row * VV);
    for (int i = threadIdx.x; i < VV / 4; i += 256) {
        float4 a = po[i];
        float2 c0 = __half22float2(pc[2 * i]);
        float2 c1 = __half22float2(pc[2 * i + 1]);
        float4 r;
        r.x = fmaf(g, a.x - c0.x, c0.x);
        r.y = fmaf(g, a.y - c0.y, c0.y);
        r.z = fmaf(g, a.z - c1.x, c1.x);
        r.w = fmaf(g, a.w - c1.y, c1.y);
        po[i] = r;
    }
}

// ---------------- launcher (three-stream overlapped graph) --------------------
extern "C" void kernel_launch(void* const* d_in, const int* in_sizes, int n_in,
                              void* d_out, int out_size)
{
    const int*   chars   = (const int*)  d_in[0];
    const float* emb     = (const float*)d_in[1];
    const float* in_proj = (const float*)d_in[2];
    const float* decays  = (const float*)d_in[3];
    const float* lin_W1  = (const float*)d_in[4];
    const float* lin_b1  = (const float*)d_in[5];
    const float* lin_W2  = (const float*)d_in[6];
    const float* lin_b2  = (const float*)d_in[7];
    const float* loc_W1  = (const float*)d_in[8];
    const float* loc_b1  = (const float*)d_in[9];
    const float* loc_W2  = (const float*)d_in[10];
    const float* loc_b2  = (const float*)d_in[11];
    const float* gate_W  = (const float*)d_in[12];
    const float* gate_b  = (const float*)d_in[13];
    float* out = (float*)d_out;

    float *px, *pdrive, *psmA, *psmB;
    unsigned *pmxA, *pmxB;
    __half *ploc, *pz, *ps, *pha, *phb, *pwl, *pwc, *pw1l, *pw1c;
    cudaGetSymbolAddress((void**)&px,     g_x);
    cudaGetSymbolAddress((void**)&pdrive, g_drive);
    cudaGetSymbolAddress((void**)&ploc,   g_loc16);
    cudaGetSymbolAddress((void**)&pmxA,   g_mxA);
    cudaGetSymbolAddress((void**)&pmxB,   g_mxB);
    cudaGetSymbolAddress((void**)&psmA,   g_smA);
    cudaGetSymbolAddress((void**)&psmB,   g_smB);
    cudaGetSymbolAddress((void**)&pz,     g_z16);
    cudaGetSymbolAddress((void**)&ps,     g_s16);
    cudaGetSymbolAddress((void**)&pha,    g_ha16);
    cudaGetSymbolAddress((void**)&phb,    g_hb16);
    cudaGetSymbolAddress((void**)&pwl,    g_w16l);
    cudaGetSymbolAddress((void**)&pwc,    g_w16c);
    cudaGetSymbolAddress((void**)&pw1l,   g_w1l16);
    cudaGetSymbolAddress((void**)&pw1c,   g_w1c16);

    static cudaStream_t s1 = nullptr, s2 = nullptr;
    static cudaEvent_t eF = nullptr, e0 = nullptr, e1 = nullptr,
                       e2a = nullptr, e2b = nullptr;
    static bool init_done = false;
    if (!init_done) {
        cudaFuncSetAttribute(k_mf16<true, true, false>,
                             cudaFuncAttributeMaxDynamicSharedMemorySize, FSMEM);
        cudaFuncSetAttribute(k_mf16<false, true, true>,
                             cudaFuncAttributeMaxDynamicSharedMemorySize, FSMEM);
        cudaFuncSetAttribute(k_mf16<false, false, true>,
                             cudaFuncAttributeMaxDynamicSharedMemorySize, FSMEM);
        cudaStreamCreateWithFlags(&s1, cudaStreamNonBlocking);
        cudaStreamCreateWithFlags(&s2, cudaStreamNonBlocking);
        cudaEventCreateWithFlags(&eF, cudaEventDisableTiming);
        cudaEventCreateWithFlags(&e0, cudaEventDisableTiming);
        cudaEventCreateWithFlags(&e1, cudaEventDisableTiming);
        cudaEventCreateWithFlags(&e2a, cudaEventDisableTiming);
        cudaEventCreateWithFlags(&e2b, cudaEventDisableTiming);
        init_done = true;
    }

    // ---- capture-legal fork: s2 and s1 must descend from the capture stream --
    cudaEventRecord(eF, 0);
    cudaStreamWaitEvent(s2, eF, 0);

    // ---- s2: W2 conversions (input-only deps; DRAM-bound, hide under GEMMs) --
    k_wconvT<<<dim3(VV / 32, HH / 32), dim3(32, 8), 0, s2>>>(loc_W2, pwc, HH, VV);
    cudaEventRecord(e2a, s2);
    k_wconvT<<<dim3(VV / 32, HH / 32), dim3(32, 8), 0, s2>>>(lin_W2, pwl, HH, VV);
    cudaEventRecord(e2b, s2);

    // ---- s0 head: embed (also zeroes stat accumulators) ----------------------
    k_embed<<<RR, 64>>>(chars, emb);
    cudaEventRecord(e0, 0);
    cudaStreamWaitEvent(s1, e0, 0);

    // ---- s1: loc path --------------------------------------------------------
    k_stack<<<dim3(RR, WW), 64, 0, s1>>>();
    k_wconvT<<<dim3(HH / 32, SK / 32), dim3(32, 8), 0, s1>>>(loc_W1, pw1c, SK, HH);
    k_mf16<true, true, false><<<dim3(RR / 128, HH / 128), 256, FSMEM, s1>>>(
        ps, pw1c, loc_b1, nullptr, phb, SK, HH, nullptr, nullptr);
    cudaStreamWaitEvent(s1, e2a, 0);
    k_mf16<false, true, true><<<dim3(RR / 128, VV / 128), 256, FSMEM, s1>>>(
        phb, pwc, loc_b2, nullptr, ploc, HH, VV, pmxB, psmB);
    cudaEventRecord(e1, s1);

    // ---- s0: lin path --------------------------------------------------------
    k_gemm<<<dim3(MM / GBN, RR / GBM), 256>>>(px, in_proj, pdrive, MM, EE);
    k_scan<<<2, 256>>>(decays);
    k_wconvT<<<dim3(HH / 32, ZK / 32), dim3(32, 8)>>>(lin_W1, pw1l, ZK, HH);
    k_mf16<true, true, false><<<dim3(RR / 128, HH / 128), 256, FSMEM>>>(
        pz, pw1l, lin_b1, nullptr, pha, ZK, HH, nullptr, nullptr);
    cudaStreamWaitEvent(0, e2b, 0);
    k_mf16<false, false, true><<<dim3(RR / 128, VV / 128), 256, FSMEM>>>(
        pha, pwl, lin_b2, out, nullptr, HH, VV, pmxA, psmA);

    // ---- join + mix (s0) -----------------------------------------------------
    cudaStreamWaitEvent(0, e1, 0);
    k_mix<<<RR, 256>>>(out, gate_W, gate_b);
}

// round 16
// speedup vs baseline: 1.2830x; 1.0127x over previous
#include <cuda_runtime.h>
#include <cuda_bf16.h>
#include <cuda_fp16.h>
#include <math.h>
#include <stdint.h>

// Problem dims (fixed)
#define BB 2
#define TT 1024
#define RR 2048          // B*T rows
#define EE 256
#define MM 256
#define HH 1024
#define VV 32000
#define WW 8
#define ZK 512           // M+E
#define SK 2048          // W*E

// ================= PTX helpers (arch-agnostic only!) ==========================
__device__ __forceinline__ uint32_t smem_u32(const void* p) {
    uint32_t a;
    asm("{ .reg .u64 t; cvta.to.shared.u64 t, %1; cvt.u32.u64 %0, t; }" : "=r"(a) : "l"(p));
    return a;
}
__device__ __forceinline__ void cp16(uint32_t saddr, const void* g) {
    asm volatile("cp.async.cg.shared.global [%0], [%1], 16;\n" :: "r"(saddr), "l"(g));
}
#define CP_COMMIT() asm volatile("cp.async.commit_group;\n" ::: "memory")
#define CP_WAIT(n)  asm volatile("cp.async.wait_group %0;\n" :: "n"(n) : "memory")

__device__ __forceinline__ void ldmx4(uint32_t* r, uint32_t addr) {
    asm volatile("ldmatrix.sync.aligned.m8n8.x4.shared.b16 {%0,%1,%2,%3}, [%4];"
        : "=r"(r[0]), "=r"(r[1]), "=r"(r[2]), "=r"(r[3]) : "r"(addr));
}
__device__ __forceinline__ void mma_f16(float* c, const uint32_t* a,
                                        uint32_t b0, uint32_t b1) {
    asm volatile("mma.sync.aligned.m16n8k16.row.col.f32.f16.f16.f32 "
        "{%0,%1,%2,%3}, {%4,%5,%6,%7}, {%8,%9}, {%0,%1,%2,%3};"
        : "+f"(c[0]), "+f"(c[1]), "+f"(c[2]), "+f"(c[3])
        : "r"(a[0]), "r"(a[1]), "r"(a[2]), "r"(a[3]), "r"(b0), "r"(b1));
}
// ordered-uint encoding for float atomicMax
__device__ __forceinline__ unsigned enc_max(float x) {
    unsigned b = __float_as_uint(x);
    return (b >> 31) ? ~b : (b | 0x80000000u);
}
__device__ __forceinline__ float dec_max(unsigned e) {
    return (e & 0x80000000u) ? __uint_as_float(e & 0x7fffffffu) : __uint_as_float(~e);
}

// ---------------- scratch (device globals; no allocation allowed) -------------
__device__ float g_x[RR * EE];
__device__ float g_drive[RR * MM];
__device__ __half g_lin16[(size_t)RR * VV];     // lin logits (fp16)
__device__ __half g_loc16[(size_t)RR * VV];     // loc logits (fp16)
// fused logit-stat accumulators: per row {se, sl, sum, sq} + encoded max
__device__ unsigned g_mxA[RR];
__device__ unsigned g_mxB[RR];
__device__ float g_smA[RR * 4];
__device__ float g_smB[RR * 4];
// fp16 activations
__device__ __half g_z16[RR * ZK];               // [states | x]
__device__ __half g_s16[RR * SK];               // windowed stack
__device__ __half g_ha16[RR * HH];              // lin hidden
__device__ __half g_hb16[RR * HH];              // loc hidden
// fp16 transposed weights [N,K]
__device__ __half g_w16l[(size_t)VV * HH];      // lin_W2^T
__device__ __half g_w16c[(size_t)VV * HH];      // loc_W2^T
__device__ __half g_w1l16[HH * ZK];             // lin_W1^T
__device__ __half g_w1c16[(size_t)HH * SK];     // loc_W1^T

// -------- embed: x fp32 + z[:,256:512] fp16 + zero stat accumulators ----------
__global__ void k_embed(const int* __restrict__ chars, const float* __restrict__ emb) {
    int row = blockIdx.x;
    int i = threadIdx.x;
    if (i == 0) { g_mxA[row] = 0x007fffffu; g_mxB[row] = 0x007fffffu; }  // enc(-inf)
    if (i < 4) { g_smA[row * 4 + i] = 0.f; g_smB[row * 4 + i] = 0.f; }
    int c = chars[row];
    const float4* src = (const float4*)(emb + (size_t)c * EE);
    float4* dx = (float4*)(g_x + (size_t)row * EE);
    float4 v = src[i];
    dx[i] = v;
    __half2* dz = (__half2*)(g_z16 + (size_t)row * ZK + MM + i * 4);
    dz[0] = __floats2half2_rn(v.x, v.y);
    dz[1] = __floats2half2_rn(v.z, v.w);
}

// -------- decay scan -> z[:,0:256] fp16 ---------------------------------------
__global__ void k_scan(const float* __restrict__ decays) {
    int idx = blockIdx.x * blockDim.x + threadIdx.x;
    if (idx >= BB * MM) return;
    int b = idx >> 8;
    int m = idx & 255;
    float d = decays[m];
    float s = 0.f;
    const float* dr = g_drive + (size_t)b * TT * MM + m;
    __half* z = g_z16 + (size_t)b * TT * ZK + m;
    for (int t = 0; t < TT; t++) {
        s = fmaf(d, s, dr[(size_t)t * MM]);
        z[(size_t)t * ZK] = __float2half_rn(s);
    }
}

// -------- windowed stack -> fp16 ----------------------------------------------
__global__ void k_stack() {
    int row = blockIdx.x;
    int o = blockIdx.y;
    int t = row & (TT - 1);
    __half2* d = (__half2*)(g_s16 + (size_t)row * SK + o * EE + threadIdx.x * 4);
    if (t - o >= 0) {
        float4 v = ((const float4*)(g_x + (size_t)(row - o) * EE))[threadIdx.x];
        d[0] = __floats2half2_rn(v.x, v.y);
        d[1] = __floats2half2_rn(v.z, v.w);
    } else {
        __half2 zz = __floats2half2_rn(0.f, 0.f);
        d[0] = zz; d[1] = zz;
    }
}

// ---------------- SIMT fp32 GEMM (drive only) ---------------------------------
#define GBM 128
#define GBN 128
#define GBK 16
__global__ __launch_bounds__(256, 2) void k_gemm(
    const float* __restrict__ A, const float* __restrict__ B,
    float* __restrict__ C, int Ndim, int Kdim)
{
    __shared__ float As[GBK][GBM + 4];
    __shared__ float Bs[GBK][GBN + 4];
    int tid = threadIdx.x;
    int m0 = blockIdx.y * GBM;
    int n0 = blockIdx.x * GBN;
    int ty = tid >> 4, tx = tid & 15;
    float acc[8][8];
#pragma unroll
    for (int i = 0; i < 8; i++)
#pragma unroll
        for (int j = 0; j < 8; j++) acc[i][j] = 0.f;
    for (int k0 = 0; k0 < Kdim; k0 += GBK) {
#pragma unroll
        for (int r = 0; r < 2; r++) {
            int idx = tid + r * 256;
            int ar = idx >> 2, ac4 = idx & 3;
            float4 va = *(const float4*)(A + (size_t)(m0 + ar) * Kdim + k0 + ac4 * 4);
            As[ac4 * 4 + 0][ar] = va.x;
            As[ac4 * 4 + 1][ar] = va.y;
            As[ac4 * 4 + 2][ar] = va.z;
            As[ac4 * 4 + 3][ar] = va.w;
            int br = idx >> 5, bc4 = idx & 31;
            float4 vb = *(const float4*)(B + (size_t)(k0 + br) * Ndim + n0 + bc4 * 4);
            *(float4*)&Bs[br][bc4 * 4] = vb;
        }
        __syncthreads();
#pragma unroll
        for (int kk = 0; kk < GBK; kk++) {
            float a[8], b[8];
            *(float4*)&a[0] = *(const float4*)&As[kk][ty * 8];
            *(float4*)&a[4] = *(const float4*)&As[kk][ty * 8 + 4];
            *(float4*)&b[0] = *(const float4*)&Bs[kk][tx * 8];
            *(float4*)&b[4] = *(const float4*)&Bs[kk][tx * 8 + 4];
#pragma unroll
            for (int i = 0; i < 8; i++)
#pragma unroll
                for (int j = 0; j < 8; j++)
                    acc[i][j] = fmaf(a[i], b[j], acc[i][j]);
        }
        __syncthreads();
    }
#pragma unroll
    for (int i = 0; i < 8; i++) {
        int m = m0 + ty * 8 + i;
#pragma unroll
        for (int j = 0; j < 8; j += 4) {
            int n = n0 + tx * 8 + j;
            float4 v;
            v.x = acc[i][j + 0]; v.y = acc[i][j + 1];
            v.z = acc[i][j + 2]; v.w = acc[i][j + 3];
            *(float4*)(C + (size_t)m * Ndim + n) = v;
        }
    }
}

// ---------- transpose + convert W[Krows,Ncols] -> Wt[N,K] fp16 ----------------
__global__ void k_wconvT(const float* __restrict__ Wsrc,
                         __half* __restrict__ T, int Krows, int Ncols) {
    __shared__ float tile[32][33];
    int n0 = blockIdx.x * 32;
    int k0 = blockIdx.y * 32;
    int tx = threadIdx.x, ty = threadIdx.y;
#pragma unroll
    for (int r = 0; r < 32; r += 8)
        tile[ty + r][tx] = Wsrc[(size_t)(k0 + ty + r) * Ncols + n0 + tx];
    __syncthreads();
#pragma unroll
    for (int r = 0; r < 32; r += 8)
        T[(size_t)(n0 + ty + r) * Krows + k0 + tx] = __float2half_rn(tile[tx][ty + r]);
}

// ===== unified fp16 GEMM: CTA 128x128, 256 thr, BK=32, 4-stage, 2 CTAs/SM =====
// Ch[M,N] = act(A[M,K] @ B[N,K]^T + bias) in fp16; optional fused per-row
// softmax-stat accumulation (max/se/sl/sum/sq, computed in fp32) via atomics.
#define ROWP 80
#define FTILA (128 * ROWP)               // 10240
#define FSTG (2 * FTILA)                 // 20480
#define FSMEM (4 * FSTG)                 // 81920

template<bool RELU, bool STATS>
__global__ __launch_bounds__(256, 2) void k_mf16(
    const __half* __restrict__ A, const __half* __restrict__ B,
    const float* __restrict__ bias, __half* __restrict__ Ch, int Kdim, int ldC,
    unsigned* __restrict__ rmx, float* __restrict__ rsm)
{
    extern __shared__ char smem[];
    uint32_t sb = smem_u32(smem);
    int tid = threadIdx.x;
    int w = tid >> 5, lane = tid & 31;
    int wm = w & 3, wn = w >> 2;            // warp tile 32x64
    int m0 = blockIdx.x * 128;
    int n0 = blockIdx.y * 128;
    int nit = Kdim / 32;

    float acc[2][8][4];
#pragma unroll
    for (int a = 0; a < 2; a++)
#pragma unroll
        for (int b = 0; b < 8; b++)
#pragma unroll
            for (int c = 0; c < 4; c++) acc[a][b][c] = 0.f;

    auto load_stage = [&](int s, int k0) {
        uint32_t base = sb + s * FSTG;
#pragma unroll
        for (int t = 0; t < 2; t++) {
            int idx = tid + t * 256;
            int r = idx >> 2, c = idx & 3;
            uint32_t so = (uint32_t)(r * ROWP + c * 16);
            cp16(base + so, A + (size_t)(m0 + r) * Kdim + k0 + c * 8);
            cp16(base + FTILA + so, B + (size_t)(n0 + r) * Kdim + k0 + c * 8);
        }
        CP_COMMIT();
    };

    load_stage(0, 0);
    if (nit > 1) load_stage(1, 32);
    if (nit > 2) load_stage(2, 64);

    int lr = lane & 15, lc = lane >> 4;
#pragma unroll 1
    for (int i = 0; i < nit; i++) {
        if (i + 3 <= nit) { CP_WAIT(2); }
        else if (i + 2 == nit) { CP_WAIT(1); }
        else { CP_WAIT(0); }
        __syncthreads();
        if (i + 3 < nit) load_stage((i + 3) & 3, (i + 3) * 32);

        uint32_t base = sb + (i & 3) * FSTG;
#pragma unroll
        for (int kh = 0; kh < 2; kh++) {
            uint32_t colB = (uint32_t)((kh * 16 + lc * 8) * 2);
            uint32_t ra[2][4], rb[4][4];
#pragma unroll
            for (int mt = 0; mt < 2; mt++)
                ldmx4(ra[mt], base + (uint32_t)((wm * 32 + mt * 16 + lr) * ROWP) + colB);
#pragma unroll
            for (int np = 0; np < 4; np++)
                ldmx4(rb[np], base + FTILA +
                      (uint32_t)((wn * 64 + np * 16 + lr) * ROWP) + colB);
#pragma unroll
            for (int mt = 0; mt < 2; mt++)
#pragma unroll
                for (int np = 0; np < 4; np++) {
                    mma_f16(acc[mt][2 * np],     ra[mt], rb[np][0], rb[np][2]);
                    mma_f16(acc[mt][2 * np + 1], ra[mt], rb[np][1], rb[np][3]);
                }
        }
        // no bottom barrier: next iter's top barrier orders laggards vs the
        // stage overwritten then (4-deep ring)
    }

    int qr = lane >> 2, qc = lane & 3;
    float pmx[2][2], pse[2][2], psl[2][2], psum[2][2], psq[2][2];
    if (STATS) {
#pragma unroll
        for (int mt = 0; mt < 2; mt++)
#pragma unroll
            for (int hh = 0; hh < 2; hh++) {
                pmx[mt][hh] = -INFINITY; pse[mt][hh] = 0.f; psl[mt][hh] = 0.f;
                psum[mt][hh] = 0.f; psq[mt][hh] = 0.f;
            }
    }
#pragma unroll
    for (int mt = 0; mt < 2; mt++) {
        int r0 = m0 + wm * 32 + mt * 16 + qr;
#pragma unroll
        for (int nt = 0; nt < 8; nt++) {
            int cidx = n0 + wn * 64 + nt * 8 + qc * 2;
            float b0 = __ldg(bias + cidx), b1 = __ldg(bias + cidx + 1);
            float v00 = acc[mt][nt][0] + b0, v01 = acc[mt][nt][1] + b1;
            float v10 = acc[mt][nt][2] + b0, v11 = acc[mt][nt][3] + b1;
            if (RELU) {
                v00 = fmaxf(v00, 0.f); v01 = fmaxf(v01, 0.f);
                v10 = fmaxf(v10, 0.f); v11 = fmaxf(v11, 0.f);
            }
            *(__half2*)(Ch + (size_t)r0 * ldC + cidx) = __floats2half2_rn(v00, v01);
            *(__half2*)(Ch + (size_t)(r0 + 8) * ldC + cidx) = __floats2half2_rn(v10, v11);
            if (STATS) {
                float e;
                pmx[mt][0] = fmaxf(pmx[mt][0], fmaxf(v00, v01));
                e = __expf(v00); pse[mt][0] += e; psl[mt][0] += e * v00;
                e = __expf(v01); pse[mt][0] += e; psl[mt][0] += e * v01;
                psum[mt][0] += v00 + v01; psq[mt][0] += v00 * v00 + v01 * v01;
                pmx[mt][1] = fmaxf(pmx[mt][1], fmaxf(v10, v11));
                e = __expf(v10); pse[mt][1] += e; psl[mt][1] += e * v10;
                e = __expf(v11); pse[mt][1] += e; psl[mt][1] += e * v11;
                psum[mt][1] += v10 + v11; psq[mt][1] += v10 * v10 + v11 * v11;
            }
        }
    }
    if (STATS) {
#pragma unroll
        for (int o = 1; o <= 2; o <<= 1) {
#pragma unroll
            for (int mt = 0; mt < 2; mt++)
#pragma unroll
                for (int hh = 0; hh < 2; hh++) {
                    pmx[mt][hh]  = fmaxf(pmx[mt][hh], __shfl_xor_sync(0xffffffffu, pmx[mt][hh], o));
                    pse[mt][hh]  += __shfl_xor_sync(0xffffffffu, pse[mt][hh], o);
                    psl[mt][hh]  += __shfl_xor_sync(0xffffffffu, psl[mt][hh], o);
                    psum[mt][hh] += __shfl_xor_sync(0xffffffffu, psum[mt][hh], o);
                    psq[mt][hh]  += __shfl_xor_sync(0xffffffffu, psq[mt][hh], o);
                }
        }
        if (qc == 0) {
#pragma unroll
            for (int mt = 0; mt < 2; mt++)
#pragma unroll
                for (int hh = 0; hh < 2; hh++) {
                    int r = m0 + wm * 32 + mt * 16 + qr + hh * 8;
                    atomicMax(rmx + r, enc_max(pmx[mt][hh]));
                    atomicAdd(rsm + r * 4 + 0, pse[mt][hh]);
                    atomicAdd(rsm + r * 4 + 1, psl[mt][hh]);
                    atomicAdd(rsm + r * 4 + 2, psum[mt][hh]);
                    atomicAdd(rsm + r * 4 + 3, psq[mt][hh]);
                }
        }
    }
}

// ------------- gate from fused accumulators + mix (both logits fp16) ----------
__global__ void k_mix(float* __restrict__ out,
                      const float* __restrict__ gw, const float* __restrict__ gb)
{
    int row = blockIdx.x;
    float seA = g_smA[row * 4 + 0], slA = g_smA[row * 4 + 1];
    float smA = g_smA[row * 4 + 2], sqA = g_smA[row * 4 + 3];
    float seB = g_smB[row * 4 + 0], slB = g_smB[row * 4 + 1];
    float smB = g_smB[row * 4 + 2], sqB = g_smB[row * 4 + 3];
    float mxA = dec_max(g_mxA[row]);
    float mxB = dec_max(g_mxB[row]);
    float entA = logf(seA) - slA / seA;
    float entB = logf(seB) - slB / seB;
    float mA = smA * (1.f / VV), mB = smB * (1.f / VV);
    float varA = sqA * (1.f / VV) - mA * mA;
    float varB = sqB * (1.f / VV) - mB * mB;
    float z = __ldg(gb);
    z = fmaf(entA, __ldg(gw + 0), z);
    z = fmaf(mxA,  __ldg(gw + 1), z);
    z = fmaf(varA, __ldg(gw + 2), z);
    z = fmaf(entB, __ldg(gw + 3), z);
    z = fmaf(mxB,  __ldg(gw + 4), z);
    z = fmaf(varB, __ldg(gw + 5), z);
    float g = 1.f / (1.f + expf(-z));

    float4* po = (float4*)(out + (size_t)row * VV);
    const __half2* pa = (const __half2*)(g_lin16 + (size_t)row * VV);
    const __half2* pc = (const __half2*)(g_loc16 + (size_t)row * VV);
    for (int i = threadIdx.x; i < VV / 4; i += 256) {
        float2 a0 = __half22float2(pa[2 * i]);
        float2 a1 = __half22float2(pa[2 * i + 1]);
        float2 c0 = __half22float2(pc[2 * i]);
        float2 c1 = __half22float2(pc[2 * i + 1]);
        float4 r;
        r.x = fmaf(g, a0.x - c0.x, c0.x);
        r.y = fmaf(g, a0.y - c0.y, c0.y);
        r.z = fmaf(g, a1.x - c1.x, c1.x);
        r.w = fmaf(g, a1.y - c1.y, c1.y);
        po[i] = r;
    }
}

// ---------------- launcher (four-stream overlapped graph) ---------------------
extern "C" void kernel_launch(void* const* d_in, const int* in_sizes, int n_in,
                              void* d_out, int out_size)
{
    const int*   chars   = (const int*)  d_in[0];
    const float* emb     = (const float*)d_in[1];
    const float* in_proj = (const float*)d_in[2];
    const float* decays  = (const float*)d_in[3];
    const float* lin_W1  = (const float*)d_in[4];
    const float* lin_b1  = (const float*)d_in[5];
    const float* lin_W2  = (const float*)d_in[6];
    const float* lin_b2  = (const float*)d_in[7];
    const float* loc_W1  = (const float*)d_in[8];
    const float* loc_b1  = (const float*)d_in[9];
    const float* loc_W2  = (const float*)d_in[10];
    const float* loc_b2  = (const float*)d_in[11];
    const float* gate_W  = (const float*)d_in[12];
    const float* gate_b  = (const float*)d_in[13];
    float* out = (float*)d_out;

    float *px, *pdrive, *psmA, *psmB;
    unsigned *pmxA, *pmxB;
    __half *plin, *ploc, *pz, *ps, *pha, *phb, *pwl, *pwc, *pw1l, *pw1c;
    cudaGetSymbolAddress((void**)&px,     g_x);
    cudaGetSymbolAddress((void**)&pdrive, g_drive);
    cudaGetSymbolAddress((void**)&plin,   g_lin16);
    cudaGetSymbolAddress((void**)&ploc,   g_loc16);
    cudaGetSymbolAddress((void**)&pmxA,   g_mxA);
    cudaGetSymbolAddress((void**)&pmxB,   g_mxB);
    cudaGetSymbolAddress((void**)&psmA,   g_smA);
    cudaGetSymbolAddress((void**)&psmB,   g_smB);
    cudaGetSymbolAddress((void**)&pz,     g_z16);
    cudaGetSymbolAddress((void**)&ps,     g_s16);
    cudaGetSymbolAddress((void**)&pha,    g_ha16);
    cudaGetSymbolAddress((void**)&phb,    g_hb16);
    cudaGetSymbolAddress((void**)&pwl,    g_w16l);
    cudaGetSymbolAddress((void**)&pwc,    g_w16c);
    cudaGetSymbolAddress((void**)&pw1l,   g_w1l16);
    cudaGetSymbolAddress((void**)&pw1c,   g_w1c16);

    static cudaStream_t s1 = nullptr, s2 = nullptr, s3 = nullptr;
    static cudaEvent_t eF = nullptr, e0 = nullptr, e1 = nullptr,
                       e2a = nullptr, e2b = nullptr;
    static bool init_done = false;
    if (!init_done) {
        cudaFuncSetAttribute(k_mf16<true, false>,
                             cudaFuncAttributeMaxDynamicSharedMemorySize, FSMEM);
        cudaFuncSetAttribute(k_mf16<false, true>,
                             cudaFuncAttributeMaxDynamicSharedMemorySize, FSMEM);
        cudaStreamCreateWithFlags(&s1, cudaStreamNonBlocking);
        cudaStreamCreateWithFlags(&s2, cudaStreamNonBlocking);
        cudaStreamCreateWithFlags(&s3, cudaStreamNonBlocking);
        cudaEventCreateWithFlags(&eF, cudaEventDisableTiming);
        cudaEventCreateWithFlags(&e0, cudaEventDisableTiming);
        cudaEventCreateWithFlags(&e1, cudaEventDisableTiming);
        cudaEventCreateWithFlags(&e2a, cudaEventDisableTiming);
        cudaEventCreateWithFlags(&e2b, cudaEventDisableTiming);
        init_done = true;
    }

    // ---- capture-legal fork: side streams descend from the capture stream ----
    cudaEventRecord(eF, 0);
    cudaStreamWaitEvent(s2, eF, 0);
    cudaStreamWaitEvent(s3, eF, 0);

    // ---- s2/s3: W2 conversions in parallel (input-only deps) -----------------
    k_wconvT<<<dim3(VV / 32, HH / 32), dim3(32, 8), 0, s2>>>(loc_W2, pwc, HH, VV);
    cudaEventRecord(e2a, s2);
    k_wconvT<<<dim3(VV / 32, HH / 32), dim3(32, 8), 0, s3>>>(lin_W2, pwl, HH, VV);
    cudaEventRecord(e2b, s3);

    // ---- s0 head: embed (also zeroes stat accumulators) ----------------------
    k_embed<<<RR, 64>>>(chars, emb);
    cudaEventRecord(e0, 0);
    cudaStreamWaitEvent(s1, e0, 0);

    // ---- s1: loc path --------------------------------------------------------
    k_stack<<<dim3(RR, WW), 64, 0, s1>>>();
    k_wconvT<<<dim3(HH / 32, SK / 32), dim3(32, 8), 0, s1>>>(loc_W1, pw1c, SK, HH);
    k_mf16<true, false><<<dim3(RR / 128, HH / 128), 256, FSMEM, s1>>>(
        ps, pw1c, loc_b1, phb, SK, HH, nullptr, nullptr);
    cudaStreamWaitEvent(s1, e2a, 0);
    k_mf16<false, true><<<dim3(RR / 128, VV / 128), 256, FSMEM, s1>>>(
        phb, pwc, loc_b2, ploc, HH, VV, pmxB, psmB);
    cudaEventRecord(e1, s1);

    // ---- s0: lin path --------------------------------------------------------
    k_gemm<<<dim3(MM / GBN, RR / GBM), 256>>>(px, in_proj, pdrive, MM, EE);
    k_scan<<<2, 256>>>(decays);
    k_wconvT<<<dim3(HH / 32, ZK / 32), dim3(32, 8)>>>(lin_W1, pw1l, ZK, HH);
    k_mf16<true, false><<<dim3(RR / 128, HH / 128), 256, FSMEM>>>(
        pz, pw1l, lin_b1, pha, ZK, HH, nullptr, nullptr);
    cudaStreamWaitEvent(0, e2b, 0);
    k_mf16<false, true><<<dim3(RR / 128, VV / 128), 256, FSMEM>>>(
        pha, pwl, lin_b2, plin, HH, VV, pmxA, psmA);

    // ---- join + mix (s0) -----------------------------------------------------
    cudaStreamWaitEvent(0, e1, 0);
    k_mix<<<RR, 256>>>(out, gate_W, gate_b);
}